// round 11
// baseline (speedup 1.0000x reference)
#include <cuda_runtime.h>
#include <cuda_bf16.h>
#include <cstdint>
#include <math.h>
#define HD 1024
#define NBS 64
#define F_XB 0UL
#define F_QT (F_XB+33554432UL)
#define F_L  (F_QT+1048576UL)
#define F_CB (F_L+4194304UL)
#define F_TOT (F_CB+4194304UL)
__device__ float g_f[F_TOT];
__device__ __nv_bfloat16 g_b[184549376UL];
__device__ float sp_partial[NBS*HD];
__device__ float sp_u[HD], sp_v[HD], sp_w[HD];
__device__ float sp_norm;
__device__ float d_rsigma[3];
__device__ unsigned bar_cnt = 0, bar_gen = 0;

__device__ __forceinline__ void gridbar() {
    __syncthreads(); __threadfence();
    if (threadIdx.x == 0) {
        unsigned g = atomicAdd(&bar_gen, 0u);
        if (atomicAdd(&bar_cnt, 1u) == NBS - 1u) {
            bar_cnt = 0u; __threadfence(); atomicExch(&bar_gen, g + 1u);
        } else while (atomicAdd(&bar_gen, 0u) == g) __nanosleep(64);
    }
    __syncthreads();
}

__global__ void __launch_bounds__(256) spectral_kernel(const float* __restrict__ WA,
    const float* __restrict__ WB, const float* __restrict__ WC) {
    __shared__ float red[256];
    const int tid = threadIdx.x, bid = blockIdx.x, gtid = bid*256 + tid;
    const float* Ws[3] = {WA, WB, WC};
    for (int m = 0; m < 3; m++) {
        const float* W = Ws[m];
        if (gtid < HD) sp_u[gtid] = 0.03125f;
        gridbar();
        for (int it = 0; it <= 10; it++) {
            const int i0 = bid*16;
            float a0=0,a1=0,a2=0,a3=0;
            for (int i = i0; i < i0+16; i++) {
                float ui = __ldcg(&sp_u[i]);
                const float* Wr = W + (size_t)i*HD;
                a0 += Wr[tid]*ui; a1 += Wr[tid+256]*ui;
                a2 += Wr[tid+512]*ui; a3 += Wr[tid+768]*ui;
            }
            sp_partial[bid*HD+tid]=a0; sp_partial[bid*HD+tid+256]=a1;
            sp_partial[bid*HD+tid+512]=a2; sp_partial[bid*HD+tid+768]=a3;
            gridbar();
            if (gtid < HD) { float s=0; for (int b=0;b<NBS;b++) s += __ldcg(&sp_partial[b*HD+gtid]); sp_v[gtid]=s; }
            gridbar();
            if (bid == 0) {
                float s=0;
                #pragma unroll
                for (int q=0;q<4;q++){ float x=__ldcg(&sp_v[tid*4+q]); s+=x*x; }
                red[tid]=s; __syncthreads();
                for (int st=128;st>0;st>>=1){ if(tid<st) red[tid]+=red[tid+st]; __syncthreads(); }
                if (tid==0) sp_norm = sqrtf(red[0]) + 1e-12f;
            }
            gridbar();
            if (gtid < HD) sp_v[gtid] = __ldcg(&sp_v[gtid]) / __ldcg(&sp_norm);
            gridbar();
            if (it == 10) break;
            { const int warp = gtid>>5, lane = gtid&31;
              for (int i = warp; i < HD; i += (NBS*256)/32) {
                const float* Wr = W + (size_t)i*HD;
                float s=0;
                for (int j=lane;j<HD;j+=32) s += Wr[j]*__ldcg(&sp_v[j]);
                #pragma unroll
                for (int o=16;o;o>>=1) s += __shfl_xor_sync(0xffffffffu,s,o);
                if (lane==0) sp_u[i]=s;
              } }
            gridbar();
            if (bid == 0) {
                float s=0;
                #pragma unroll
                for (int q=0;q<4;q++){ float x=__ldcg(&sp_u[tid*4+q]); s+=x*x; }
                red[tid]=s; __syncthreads();
                for (int st=128;st>0;st>>=1){ if(tid<st) red[tid]+=red[tid+st]; __syncthreads(); }
                if (tid==0) sp_norm = sqrtf(red[0]) + 1e-12f;
            }
            gridbar();
            if (gtid < HD) sp_u[gtid] = __ldcg(&sp_u[gtid]) / __ldcg(&sp_norm);
            gridbar();
        }
        { const int warp = gtid>>5, lane = gtid&31;
          for (int i = warp; i < HD; i += (NBS*256)/32) {
            const float* Wr = W + (size_t)i*HD;
            float s=0;
            for (int j=lane;j<HD;j+=32) s += Wr[j]*__ldcg(&sp_v[j]);
            #pragma unroll
            for (int o=16;o;o>>=1) s += __shfl_xor_sync(0xffffffffu,s,o);
            if (lane==0) sp_w[i]=s;
          } }
        gridbar();
        if (bid == 0) {
            float s=0;
            #pragma unroll
            for (int q=0;q<4;q++) s += __ldcg(&sp_u[tid*4+q])*__ldcg(&sp_w[tid*4+q]);
            red[tid]=s; __syncthreads();
            for (int st=128;st>0;st>>=1){ if(tid<st) red[tid]+=red[tid+st]; __syncthreads(); }
            if (tid==0) d_rsigma[m] = 1.0f/red[0];
        }
        gridbar();
    }
}

__device__ __forceinline__ void split1(float v, __nv_bfloat16& h, __nv_bfloat16& l) {
    h = __float2bfloat16_rn(v);
    l = __float2bfloat16_rn(v - __bfloat162float(h));
}
__device__ __forceinline__ uint32_t s2u(const void* p) {
    uint32_t a;
    asm("{.reg .u64 t; cvta.to.shared.u64 t, %1; cvt.u32.u64 %0, t;}" : "=r"(a) : "l"(p));
    return a;
}
#define CP16(d,s) asm volatile("cp.async.cg.shared.global [%0], [%1], 16;" :: "r"(d), "l"(s))
#define CPC() asm volatile("cp.async.commit_group;")
#define CPW1() asm volatile("cp.async.wait_group 1;")
#define CPW0() asm volatile("cp.async.wait_group 0;")
#define LDSM4(r0,r1,r2,r3,a) asm volatile("ldmatrix.sync.aligned.m8n8.x4.shared.b16 {%0,%1,%2,%3}, [%4];" \
    : "=r"(r0),"=r"(r1),"=r"(r2),"=r"(r3) : "r"(a))
#define MMA(d,a,b0,b1) asm volatile( \
    "mma.sync.aligned.m16n8k16.row.col.f32.bf16.bf16.f32 {%0,%1,%2,%3},{%4,%5,%6,%7},{%8,%9},{%0,%1,%2,%3};" \
    : "+f"(d[0]),"+f"(d[1]),"+f"(d[2]),"+f"(d[3]) \
    : "r"(a[0]),"r"(a[1]),"r"(a[2]),"r"(a[3]),"r"(b0),"r"(b1))

__global__ void splitk(const float* __restrict__ src, __nv_bfloat16* __restrict__ oh,
                       __nv_bfloat16* __restrict__ ol, int sidx) {
    float f = sidx >= 0 ? d_rsigma[sidx] : 1.f;
    size_t i = ((size_t)blockIdx.x*256 + threadIdx.x)*4;
    float4 v = *(const float4*)(src + i);
    __nv_bfloat16 h0,l0,h1,l1,h2,l2,h3,l3;
    split1(v.x*f,h0,l0); split1(v.y*f,h1,l1); split1(v.z*f,h2,l2); split1(v.w*f,h3,l3);
    __nv_bfloat162 a,b;
    a.x=h0;a.y=h1;b.x=h2;b.y=h3;
    *(__nv_bfloat162*)(oh+i)=a; *(__nv_bfloat162*)(oh+i+2)=b;
    a.x=l0;a.y=l1;b.x=l2;b.y=l3;
    *(__nv_bfloat162*)(ol+i)=a; *(__nv_bfloat162*)(ol+i+2)=b;
}

__global__ void tsplit(const float* __restrict__ W, __nv_bfloat16* __restrict__ oh,
                       __nv_bfloat16* __restrict__ ol, int sidx) {
    __shared__ float t[32][33];
    float s = d_rsigma[sidx];
    int x = blockIdx.x*32 + threadIdx.x, y0 = blockIdx.y*32;
    #pragma unroll
    for (int i = threadIdx.y; i < 32; i += 8)
        t[i][threadIdx.x] = W[(size_t)(y0+i)*HD + x];
    __syncthreads();
    int ox = y0 + threadIdx.x, oy0 = blockIdx.x*32;
    #pragma unroll
    for (int i = threadIdx.y; i < 32; i += 8) {
        __nv_bfloat16 h,l; split1(t[threadIdx.x][i]*s,h,l);
        oh[(size_t)(oy0+i)*HD + ox] = h;
        ol[(size_t)(oy0+i)*HD + ox] = l;
    }
}

#define STR 40
// R6-proven mainloop: 256 thr, 4x2 warp grid, 32x64/warp, BK=32, cp.async x2, occ 2.
// Stage layout per 40960B: Ah+0, Al+10240, Bh+20480, Bl+30720.
// CHUNK=8 mappings. mode 0: Cf?/Oh? at r. mode 1: xb scatter (+bf16 if row<4096). mode 2: pass3.
__global__ void __launch_bounds__(256,2) mmagemm(
    const __nv_bfloat16* __restrict__ Ahh, const __nv_bfloat16* __restrict__ All,
    const __nv_bfloat16* __restrict__ Bhh, const __nv_bfloat16* __restrict__ Bll,
    const float* __restrict__ Add, float* __restrict__ Cf,
    __nv_bfloat16* __restrict__ Oh, __nv_bfloat16* __restrict__ Ol,
    __nv_bfloat16* __restrict__ O2h, __nv_bfloat16* __restrict__ O2l,
    int mode, int jp)
{
    extern __shared__ __nv_bfloat16 smx[];
    const int tid=threadIdx.x, lane=tid&31, wid=tid>>5, wm=wid&3, wn=wid>>2;
    const int m0=blockIdx.y*128, n0=blockIdx.x*128;
    const uint32_t sb=s2u(smx);
    const __nv_bfloat16* srcs[4]={Ahh,All,Bhh,Bll};
    float acc[2][8][4];
    #pragma unroll
    for (int i=0;i<2;i++)
        #pragma unroll
        for (int j=0;j<8;j++)
            #pragma unroll
            for (int q=0;q<4;q++) acc[i][j][q]=0.f;
    const int lr=tid>>1, lc=(tid&1)*16;
    auto ldst = [&](int kt, int st){
        const int k0 = kt*32;
        #pragma unroll
        for (int a=0;a<4;a++) {
            int row = (a<2 ? m0 : n0) + lr;
            const char* s = (const char*)(srcs[a] + (size_t)row*1024 + k0 + lc);
            uint32_t d = sb + (uint32_t)(st*40960 + a*10240 + (lr*STR+lc)*2);
            CP16(d, s); CP16(d+16, s+16);
        }
    };
    ldst(0,0); CPC();
    for (int kt=0; kt<32; kt++) {
        if (kt<31) { ldst(kt+1,(kt+1)&1); CPC(); CPW1(); } else CPW0();
        __syncthreads();
        const uint32_t ab = sb + (kt&1)*40960;
        #pragma unroll
        for (int kh=0;kh<2;kh++) {
            uint32_t ah[2][4], al[2][4];
            #pragma unroll
            for (int ti=0;ti<2;ti++) {
                uint32_t ad = ab + (uint32_t)(((wm*32+ti*16+(lane&15))*STR + kh*16+(lane>>4)*8)*2);
                LDSM4(ah[ti][0],ah[ti][1],ah[ti][2],ah[ti][3], ad);
                LDSM4(al[ti][0],al[ti][1],al[ti][2],al[ti][3], ad+10240);
            }
            #pragma unroll
            for (int q=0;q<4;q++) {
                uint32_t bd = ab + 20480u + (uint32_t)(((wn*64+q*16+(lane&7)+((lane>>4)&1)*8)*STR + kh*16+((lane>>3)&1)*8)*2);
                uint32_t h0,h1,h2,h3,l0,l1,l2,l3;
                LDSM4(h0,h1,h2,h3, bd);
                LDSM4(l0,l1,l2,l3, bd+10240);
                #pragma unroll
                for (int ti=0;ti<2;ti++) {
                    MMA(acc[ti][q*2],   ah[ti], h0,h1);
                    MMA(acc[ti][q*2],   ah[ti], l0,l1);
                    MMA(acc[ti][q*2],   al[ti], h0,h1);
                    MMA(acc[ti][q*2+1], ah[ti], h2,h3);
                    MMA(acc[ti][q*2+1], ah[ti], l2,l3);
                    MMA(acc[ti][q*2+1], al[ti], h2,h3);
                }
            }
        }
        __syncthreads();
    }
    const int rb0 = m0 + wm*32 + (lane>>2);
    #pragma unroll
    for (int ti=0;ti<2;ti++)
    #pragma unroll
    for (int j=0;j<8;j++)
    #pragma unroll
    for (int hf=0;hf<2;hf++) {
        int r = rb0 + ti*16 + hf*8;
        int c = n0 + wn*64 + j*8 + (lane&3)*2;
        float v0=acc[ti][j][hf*2], v1=acc[ti][j][hf*2+1];
        if (Add) { float2 ad = *(const float2*)(Add+(size_t)r*1024+c); v0+=ad.x; v1+=ad.y; }
        __nv_bfloat16 h0,l0,h1,l1; split1(v0,h0,l0); split1(v1,h1,l1);
        __nv_bfloat162 ph,pl; ph.x=h0;ph.y=h1; pl.x=l0;pl.y=l1;
        if (mode==2) {
            *(__nv_bfloat162*)(Oh+(size_t)r*1024+c)=ph;
            *(__nv_bfloat162*)(Ol+(size_t)r*1024+c)=pl;
            int k=r>>5, b_=r&31;
            size_t o2=(size_t)b_*1024+(size_t)k*8+jp;
            *(float2*)(Cf+o2*1024+c)=make_float2(v0,v1);
            *(__nv_bfloat162*)(O2h+o2*1024+c)=ph;
            *(__nv_bfloat162*)(O2l+o2*1024+c)=pl;
        } else {
            size_t orow=(size_t)r;
            if (mode==1){ int b_=r>>10,t=r&1023,k=t>>3,jj=t&7; orow=(size_t)((((jj<<7)|k)<<5)|b_); }
            if (Cf) *(float2*)(Cf+orow*1024+c)=make_float2(v0,v1);
            if (Oh && (mode!=1 || orow<4096)) {
                *(__nv_bfloat162*)(Oh+orow*1024+c)=ph;
                *(__nv_bfloat162*)(Ol+orow*1024+c)=pl;
            }
        }
    }
}

// persistent carry: 64 CTAs, 127 steps of C_k[32,1024] = C_{k-1}*QT + L_{k-1}, + bf16 split
__global__ void __launch_bounds__(256) pcarry(const float* __restrict__ Q, float* __restrict__ Cb,
    const float* __restrict__ L, __nv_bfloat16* __restrict__ Ch, __nv_bfloat16* __restrict__ Cl) {
    __shared__ float As[32*129];
    const int tid = threadIdx.x, row = tid & 31, c0 = blockIdx.x*16 + (tid>>5)*2;
    for (int k = 1; k < 128; k++) {
        const float* A   = Cb + (size_t)(k-1)*32768;
        const float* Add = L  + (size_t)(k-1)*32768;
        float acc0 = 0.f, acc1 = 0.f;
        for (int k0 = 0; k0 < 1024; k0 += 128) {
            #pragma unroll
            for (int q = 0; q < 16; q++) {
                int l = q*256 + tid, r = l>>7, cc = l&127;
                As[r*129 + cc] = __ldcg(&A[(size_t)r*1024 + k0 + cc]);
            }
            __syncthreads();
            #pragma unroll 4
            for (int kk = 0; kk < 128; kk++) {
                float a = As[row*129 + kk];
                float2 qv = *(const float2*)(Q + (size_t)(k0+kk)*1024 + c0);
                acc0 = fmaf(a, qv.x, acc0); acc1 = fmaf(a, qv.y, acc1);
            }
            __syncthreads();
        }
        float r0 = acc0 + Add[(size_t)row*1024 + c0];
        float r1 = acc1 + Add[(size_t)row*1024 + c0 + 1];
        float* C = Cb + (size_t)k*32768;
        C[(size_t)row*1024 + c0]   = r0;
        C[(size_t)row*1024 + c0+1] = r1;
        __nv_bfloat16 h,l;
        size_t ob = (size_t)k*32768 + (size_t)row*1024 + c0;
        split1(r0,h,l); Ch[ob]=h;   Cl[ob]=l;
        split1(r1,h,l); Ch[ob+1]=h; Cl[ob+1]=l;
        gridbar();
    }
}

__global__ void zero_cb(float* c, __nv_bfloat16* ch, __nv_bfloat16* cl) {
    int i = blockIdx.x*256 + threadIdx.x;
    if (i < 32768) { c[i]=0.f; ch[i]=__float2bfloat16(0.f); cl[i]=__float2bfloat16(0.f); }
}

extern "C" void kernel_launch(void* const* d_in, const int* in_sizes, int n_in,
                              void* d_out, int out_size) {
    const float* x  = (const float*)d_in[0];
    const float* WA = (const float*)d_in[1];
    const float* WB = (const float*)d_in[2];
    const float* WC = (const float*)d_in[3];
    float* ys = (float*)d_out;
    float* hs = ys + 33554432UL;
    float* F = nullptr; cudaGetSymbolAddress((void**)&F, g_f);
    __nv_bfloat16* G = nullptr; cudaGetSymbolAddress((void**)&G, g_b);
    float *xb=F+F_XB, *QT=F+F_QT, *L=F+F_L, *Cb=F+F_CB;
    __nv_bfloat16* p = G;
    #define NXT(nm,sz) __nv_bfloat16 *nm##h=p, *nm##l=p+(sz); p += 2UL*(sz);
    NXT(X,33554432UL) NXT(WA_,1048576UL) NXT(WAT,1048576UL) NXT(WB_,1048576UL)
    NXT(WC_,1048576UL) NXT(P1,1048576UL) NXT(P1T,1048576UL) NXT(P2,1048576UL)
    NXT(P2T,1048576UL)
    NXT(XB0,4194304UL) NXT(S0,4194304UL) NXT(S1,4194304UL) NXT(CB,4194304UL)
    NXT(HS,33554432UL)
    #undef NXT

    cudaFuncSetAttribute(mmagemm, cudaFuncAttributeMaxDynamicSharedMemorySize, 81920);

    spectral_kernel<<<NBS, 256>>>(WA, WB, WC);
    splitk<<<32768,256>>>(x, Xh, Xl, -1);
    splitk<<<1024,256>>>(WA, WA_h, WA_l, 0);
    splitk<<<1024,256>>>(WB, WB_h, WB_l, 1);
    splitk<<<1024,256>>>(WC, WC_h, WC_l, 2);
    mmagemm<<<dim3(8,256),256,81920>>>(Xh,Xl, WB_h,WB_l, nullptr, xb, XB0h,XB0l, nullptr,nullptr, 1,0);
    tsplit<<<dim3(32,32), dim3(32,8)>>>(WA, WATh, WATl, 0);
    // Q = (A^8)^T: P1=A^2, P1T=(A^2)^T, P2=A^4, P2T=(A^4)^T, QT=(A^8)^T fp32
    mmagemm<<<dim3(8,8),256,81920>>>(WA_h,WA_l, WATh,WATl, nullptr,nullptr, P1h,P1l, nullptr,nullptr,0,0);
    mmagemm<<<dim3(8,8),256,81920>>>(WATh,WATl, WA_h,WA_l, nullptr,nullptr, P1Th,P1Tl, nullptr,nullptr,0,0);
    mmagemm<<<dim3(8,8),256,81920>>>(P1h,P1l, P1Th,P1Tl, nullptr,nullptr, P2h,P2l, nullptr,nullptr,0,0);
    mmagemm<<<dim3(8,8),256,81920>>>(P1Th,P1Tl, P1h,P1l, nullptr,nullptr, P2Th,P2Tl, nullptr,nullptr,0,0);
    mmagemm<<<dim3(8,8),256,81920>>>(P2Th,P2Tl, P2h,P2l, nullptr, QT, nullptr,nullptr, nullptr,nullptr,0,0);
    // pass 1: 7 local-scan steps, M=4096 (256 CTAs)
    __nv_bfloat16 *ph_=XB0h, *pl_=XB0l;
    for (int j = 1; j < 8; j++) {
        __nv_bfloat16 *dh = (j&1)?S1h:S0h, *dl = (j&1)?S1l:S0l;
        mmagemm<<<dim3(8,32),256,81920>>>(ph_,pl_, WA_h,WA_l, xb+(size_t)j*4194304UL,
            (j==7)?L:nullptr, dh,dl, nullptr,nullptr, 0,0);
        ph_=dh; pl_=dl;
    }
    // pass 2: 127 carries in ONE persistent kernel
    zero_cb<<<128,256>>>(Cb, CBh, CBl);
    pcarry<<<64,256>>>(QT, Cb, L, CBh, CBl);
    // pass 3: 8 rescan steps with true inits, scatter hs
    ph_=CBh; pl_=CBl;
    for (int j = 0; j < 8; j++) {
        __nv_bfloat16 *dh = (j&1)?S1h:S0h, *dl = (j&1)?S1l:S0l;
        mmagemm<<<dim3(8,32),256,81920>>>(ph_,pl_, WA_h,WA_l, xb+(size_t)j*4194304UL,
            hs, dh,dl, HSh,HSl, 2,j);
        ph_=dh; pl_=dl;
    }
    mmagemm<<<dim3(8,256),256,81920>>>(HSh,HSl, WC_h,WC_l, nullptr, ys, nullptr,nullptr, nullptr,nullptr, 0,0);
    (void)in_sizes; (void)n_in; (void)out_size;
}

// round 12
// speedup vs baseline: 3.0356x; 3.0356x over previous
#include <cuda_runtime.h>
#include <cuda_bf16.h>
#include <cstdint>
#include <math.h>
#define HD 1024
#define NBS 64
#define F_XB 0UL
#define F_PF (F_XB+33554432UL)
#define F_T  (F_PF+1048576UL)
#define F_U  (F_T+3145728UL)
#define F_TOT (F_U+3145728UL)
__device__ float g_f[F_TOT];
__device__ __nv_bfloat16 g_b[188743680UL];
__device__ float sp_partial[NBS*HD];
__device__ float sp_u[HD], sp_v[HD], sp_w[HD];
__device__ float sp_norm;
__device__ float d_rsigma[3];
__device__ unsigned bar_cnt = 0, bar_gen = 0;

__device__ __forceinline__ void gridbar() {
    __syncthreads(); __threadfence();
    if (threadIdx.x == 0) {
        unsigned g = atomicAdd(&bar_gen, 0u);
        if (atomicAdd(&bar_cnt, 1u) == NBS - 1u) {
            bar_cnt = 0u; __threadfence(); atomicExch(&bar_gen, g + 1u);
        } else while (atomicAdd(&bar_gen, 0u) == g) __nanosleep(64);
    }
    __syncthreads();
}

__global__ void __launch_bounds__(256) spectral_kernel(const float* __restrict__ WA,
    const float* __restrict__ WB, const float* __restrict__ WC) {
    __shared__ float red[256];
    const int tid = threadIdx.x, bid = blockIdx.x, gtid = bid*256 + tid;
    const float* Ws[3] = {WA, WB, WC};
    for (int m = 0; m < 3; m++) {
        const float* W = Ws[m];
        if (gtid < HD) sp_u[gtid] = 0.03125f;
        gridbar();
        for (int it = 0; it <= 10; it++) {
            const int i0 = bid*16;
            float a0=0,a1=0,a2=0,a3=0;
            for (int i = i0; i < i0+16; i++) {
                float ui = __ldcg(&sp_u[i]);
                const float* Wr = W + (size_t)i*HD;
                a0 += Wr[tid]*ui; a1 += Wr[tid+256]*ui;
                a2 += Wr[tid+512]*ui; a3 += Wr[tid+768]*ui;
            }
            sp_partial[bid*HD+tid]=a0; sp_partial[bid*HD+tid+256]=a1;
            sp_partial[bid*HD+tid+512]=a2; sp_partial[bid*HD+tid+768]=a3;
            gridbar();
            if (gtid < HD) { float s=0; for (int b=0;b<NBS;b++) s += __ldcg(&sp_partial[b*HD+gtid]); sp_v[gtid]=s; }
            gridbar();
            if (bid == 0) {
                float s=0;
                #pragma unroll
                for (int q=0;q<4;q++){ float x=__ldcg(&sp_v[tid*4+q]); s+=x*x; }
                red[tid]=s; __syncthreads();
                for (int st=128;st>0;st>>=1){ if(tid<st) red[tid]+=red[tid+st]; __syncthreads(); }
                if (tid==0) sp_norm = sqrtf(red[0]) + 1e-12f;
            }
            gridbar();
            if (gtid < HD) sp_v[gtid] = __ldcg(&sp_v[gtid]) / __ldcg(&sp_norm);
            gridbar();
            if (it == 10) break;
            { const int warp = gtid>>5, lane = gtid&31;
              for (int i = warp; i < HD; i += (NBS*256)/32) {
                const float* Wr = W + (size_t)i*HD;
                float s=0;
                for (int j=lane;j<HD;j+=32) s += Wr[j]*__ldcg(&sp_v[j]);
                #pragma unroll
                for (int o=16;o;o>>=1) s += __shfl_xor_sync(0xffffffffu,s,o);
                if (lane==0) sp_u[i]=s;
              } }
            gridbar();
            if (bid == 0) {
                float s=0;
                #pragma unroll
                for (int q=0;q<4;q++){ float x=__ldcg(&sp_u[tid*4+q]); s+=x*x; }
                red[tid]=s; __syncthreads();
                for (int st=128;st>0;st>>=1){ if(tid<st) red[tid]+=red[tid+st]; __syncthreads(); }
                if (tid==0) sp_norm = sqrtf(red[0]) + 1e-12f;
            }
            gridbar();
            if (gtid < HD) sp_u[gtid] = __ldcg(&sp_u[gtid]) / __ldcg(&sp_norm);
            gridbar();
        }
        { const int warp = gtid>>5, lane = gtid&31;
          for (int i = warp; i < HD; i += (NBS*256)/32) {
            const float* Wr = W + (size_t)i*HD;
            float s=0;
            for (int j=lane;j<HD;j+=32) s += Wr[j]*__ldcg(&sp_v[j]);
            #pragma unroll
            for (int o=16;o;o>>=1) s += __shfl_xor_sync(0xffffffffu,s,o);
            if (lane==0) sp_w[i]=s;
          } }
        gridbar();
        if (bid == 0) {
            float s=0;
            #pragma unroll
            for (int q=0;q<4;q++) s += __ldcg(&sp_u[tid*4+q])*__ldcg(&sp_w[tid*4+q]);
            red[tid]=s; __syncthreads();
            for (int st=128;st>0;st>>=1){ if(tid<st) red[tid]+=red[tid+st]; __syncthreads(); }
            if (tid==0) d_rsigma[m] = 1.0f/red[0];
        }
        gridbar();
    }
}

__device__ __forceinline__ void split1(float v, __nv_bfloat16& h, __nv_bfloat16& l) {
    h = __float2bfloat16_rn(v);
    l = __float2bfloat16_rn(v - __bfloat162float(h));
}
__device__ __forceinline__ uint32_t s2u(const void* p) {
    uint32_t a;
    asm("{.reg .u64 t; cvta.to.shared.u64 t, %1; cvt.u32.u64 %0, t;}" : "=r"(a) : "l"(p));
    return a;
}
#define CP16(d,s) asm volatile("cp.async.cg.shared.global [%0], [%1], 16;" :: "r"(d), "l"(s))
#define CPC() asm volatile("cp.async.commit_group;")
#define CPW1() asm volatile("cp.async.wait_group 1;")
#define CPW0() asm volatile("cp.async.wait_group 0;")
#define LDSM4(r0,r1,r2,r3,a) asm volatile("ldmatrix.sync.aligned.m8n8.x4.shared.b16 {%0,%1,%2,%3}, [%4];" \
    : "=r"(r0),"=r"(r1),"=r"(r2),"=r"(r3) : "r"(a))
#define MMA(d,a,b0,b1) asm volatile( \
    "mma.sync.aligned.m16n8k16.row.col.f32.bf16.bf16.f32 {%0,%1,%2,%3},{%4,%5,%6,%7},{%8,%9},{%0,%1,%2,%3};" \
    : "+f"(d[0]),"+f"(d[1]),"+f"(d[2]),"+f"(d[3]) \
    : "r"(a[0]),"r"(a[1]),"r"(a[2]),"r"(a[3]),"r"(b0),"r"(b1))

__global__ void splitk(const float* __restrict__ src, __nv_bfloat16* __restrict__ oh,
                       __nv_bfloat16* __restrict__ ol, int sidx) {
    float f = sidx >= 0 ? d_rsigma[sidx] : 1.f;
    size_t i = ((size_t)blockIdx.x*256 + threadIdx.x)*4;
    float4 v = *(const float4*)(src + i);
    __nv_bfloat16 h0,l0,h1,l1,h2,l2,h3,l3;
    split1(v.x*f,h0,l0); split1(v.y*f,h1,l1); split1(v.z*f,h2,l2); split1(v.w*f,h3,l3);
    __nv_bfloat162 a,b;
    a.x=h0;a.y=h1;b.x=h2;b.y=h3;
    *(__nv_bfloat162*)(oh+i)=a; *(__nv_bfloat162*)(oh+i+2)=b;
    a.x=l0;a.y=l1;b.x=l2;b.y=l3;
    *(__nv_bfloat162*)(ol+i)=a; *(__nv_bfloat162*)(ol+i+2)=b;
}

__global__ void tsplit(const float* __restrict__ W, __nv_bfloat16* __restrict__ oh,
                       __nv_bfloat16* __restrict__ ol, int sidx) {
    __shared__ float t[32][33];
    float s = sidx >= 0 ? d_rsigma[sidx] : 1.f;
    int x = blockIdx.x*32 + threadIdx.x, y0 = blockIdx.y*32;
    #pragma unroll
    for (int i = threadIdx.y; i < 32; i += 8)
        t[i][threadIdx.x] = W[(size_t)(y0+i)*HD + x];
    __syncthreads();
    int ox = y0 + threadIdx.x, oy0 = blockIdx.x*32;
    #pragma unroll
    for (int i = threadIdx.y; i < 32; i += 8) {
        __nv_bfloat16 h,l; split1(t[threadIdx.x][i]*s,h,l);
        oh[(size_t)(oy0+i)*HD + ox] = h;
        ol[(size_t)(oy0+i)*HD + ox] = l;
    }
}

#define STR 40
// R6-proven mainloop. Stage layout per 40960B: Ah+0, Al+10240, Bh+20480, Bl+30720.
// mode 0: Cf?/Oh? at r. mode 1: xb scatter (CHUNK=16; bf16 if row<2048). mode 2: pass3.
__global__ void __launch_bounds__(256,2) mmagemm(
    const __nv_bfloat16* __restrict__ Ahh, const __nv_bfloat16* __restrict__ All,
    const __nv_bfloat16* __restrict__ Bhh, const __nv_bfloat16* __restrict__ Bll,
    const float* __restrict__ Add, float* __restrict__ Cf,
    __nv_bfloat16* __restrict__ Oh, __nv_bfloat16* __restrict__ Ol,
    __nv_bfloat16* __restrict__ O2h, __nv_bfloat16* __restrict__ O2l,
    int mode, int jp)
{
    extern __shared__ __nv_bfloat16 smx[];
    const int tid=threadIdx.x, lane=tid&31, wid=tid>>5, wm=wid&3, wn=wid>>2;
    const int m0=blockIdx.y*128, n0=blockIdx.x*128;
    const uint32_t sb=s2u(smx);
    const __nv_bfloat16* srcs[4]={Ahh,All,Bhh,Bll};
    float acc[2][8][4];
    #pragma unroll
    for (int i=0;i<2;i++)
        #pragma unroll
        for (int j=0;j<8;j++)
            #pragma unroll
            for (int q=0;q<4;q++) acc[i][j][q]=0.f;
    const int lr=tid>>1, lc=(tid&1)*16;
    auto ldst = [&](int kt, int st){
        const int k0 = kt*32;
        #pragma unroll
        for (int a=0;a<4;a++) {
            int row = (a<2 ? m0 : n0) + lr;
            const char* s = (const char*)(srcs[a] + (size_t)row*1024 + k0 + lc);
            uint32_t d = sb + (uint32_t)(st*40960 + a*10240 + (lr*STR+lc)*2);
            CP16(d, s); CP16(d+16, s+16);
        }
    };
    ldst(0,0); CPC();
    for (int kt=0; kt<32; kt++) {
        if (kt<31) { ldst(kt+1,(kt+1)&1); CPC(); CPW1(); } else CPW0();
        __syncthreads();
        const uint32_t ab = sb + (kt&1)*40960;
        #pragma unroll
        for (int kh=0;kh<2;kh++) {
            uint32_t ah[2][4], al[2][4];
            #pragma unroll
            for (int ti=0;ti<2;ti++) {
                uint32_t ad = ab + (uint32_t)(((wm*32+ti*16+(lane&15))*STR + kh*16+(lane>>4)*8)*2);
                LDSM4(ah[ti][0],ah[ti][1],ah[ti][2],ah[ti][3], ad);
                LDSM4(al[ti][0],al[ti][1],al[ti][2],al[ti][3], ad+10240);
            }
            #pragma unroll
            for (int q=0;q<4;q++) {
                uint32_t bd = ab + 20480u + (uint32_t)(((wn*64+q*16+(lane&7)+((lane>>4)&1)*8)*STR + kh*16+((lane>>3)&1)*8)*2);
                uint32_t h0,h1,h2,h3,l0,l1,l2,l3;
                LDSM4(h0,h1,h2,h3, bd);
                LDSM4(l0,l1,l2,l3, bd+10240);
                #pragma unroll
                for (int ti=0;ti<2;ti++) {
                    MMA(acc[ti][q*2],   ah[ti], h0,h1);
                    MMA(acc[ti][q*2],   ah[ti], l0,l1);
                    MMA(acc[ti][q*2],   al[ti], h0,h1);
                    MMA(acc[ti][q*2+1], ah[ti], h2,h3);
                    MMA(acc[ti][q*2+1], ah[ti], l2,l3);
                    MMA(acc[ti][q*2+1], al[ti], h2,h3);
                }
            }
        }
        __syncthreads();
    }
    const int rb0 = m0 + wm*32 + (lane>>2);
    #pragma unroll
    for (int ti=0;ti<2;ti++)
    #pragma unroll
    for (int j=0;j<8;j++)
    #pragma unroll
    for (int hf=0;hf<2;hf++) {
        int r = rb0 + ti*16 + hf*8;
        int c = n0 + wn*64 + j*8 + (lane&3)*2;
        float v0=acc[ti][j][hf*2], v1=acc[ti][j][hf*2+1];
        if (Add) { float2 ad = *(const float2*)(Add+(size_t)r*1024+c); v0+=ad.x; v1+=ad.y; }
        __nv_bfloat16 h0,l0,h1,l1; split1(v0,h0,l0); split1(v1,h1,l1);
        __nv_bfloat162 ph,pl; ph.x=h0;ph.y=h1; pl.x=l0;pl.y=l1;
        if (mode==2) {
            *(__nv_bfloat162*)(Oh+(size_t)r*1024+c)=ph;
            *(__nv_bfloat162*)(Ol+(size_t)r*1024+c)=pl;
            int k=r>>5, b_=r&31;
            size_t o2=(size_t)b_*1024+(size_t)k*16+jp;
            *(float2*)(Cf+o2*1024+c)=make_float2(v0,v1);
            *(__nv_bfloat162*)(O2h+o2*1024+c)=ph;
            *(__nv_bfloat162*)(O2l+o2*1024+c)=pl;
        } else {
            size_t orow=(size_t)r;
            if (mode==1){ int b_=r>>10,t=r&1023,k=t>>4,jj=t&15; orow=(size_t)((((jj<<6)|k)<<5)|b_); }
            if (Cf) *(float2*)(Cf+orow*1024+c)=make_float2(v0,v1);
            if (Oh && (mode!=1 || orow<2048)) {
                *(__nv_bfloat162*)(Oh+orow*1024+c)=ph;
                *(__nv_bfloat162*)(Ol+orow*1024+c)=pl;
            }
        }
    }
}

__global__ void copy3(float* df, __nv_bfloat16* dh, __nv_bfloat16* dl,
    const float* sf, const __nv_bfloat16* sh, const __nv_bfloat16* sl, int n) {
    int i = blockIdx.x*256 + threadIdx.x;
    if (i < n) { df[i]=sf[i]; dh[i]=sh[i]; dl[i]=sl[i]; }
}
__global__ void zero3(float* f, __nv_bfloat16* h, __nv_bfloat16* l, int n) {
    int i = blockIdx.x*256 + threadIdx.x;
    if (i < n) { f[i]=0.f; h[i]=__float2bfloat16(0.f); l[i]=__float2bfloat16(0.f); }
}

extern "C" void kernel_launch(void* const* d_in, const int* in_sizes, int n_in,
                              void* d_out, int out_size) {
    const float* x  = (const float*)d_in[0];
    const float* WA = (const float*)d_in[1];
    const float* WB = (const float*)d_in[2];
    const float* WC = (const float*)d_in[3];
    float* ys = (float*)d_out;
    float* hs = ys + 33554432UL;
    float* F = nullptr; cudaGetSymbolAddress((void**)&F, g_f);
    __nv_bfloat16* G = nullptr; cudaGetSymbolAddress((void**)&G, g_b);
    float *xb=F+F_XB, *Pf=F+F_PF, *Tf=F+F_T, *Uf=F+F_U;
    __nv_bfloat16* p = G;
    #define NXT(nm,sz) __nv_bfloat16 *nm##h=p, *nm##l=p+(sz); p += 2UL*(sz);
    NXT(X,33554432UL) NXT(WA_,1048576UL) NXT(WAT,1048576UL) NXT(WB_,1048576UL)
    NXT(WC_,1048576UL)
    __nv_bfloat16 *Ph[10], *Pl[10];
    Ph[0]=WA_h; Pl[0]=WA_l;
    for (int r=1;r<=9;r++){ Ph[r]=p; Pl[r]=p+1048576UL; p+=2097152UL; }
    NXT(PT,1048576UL)
    NXT(XB0,2097152UL) NXT(S0,2097152UL) NXT(S1,2097152UL)
    __nv_bfloat16 *Th=p, *Tl=p+3145728UL; p+=6291456UL;
    __nv_bfloat16 *Uh=p, *Ul=p+3145728UL; p+=6291456UL;
    NXT(HS,33554432UL)
    #undef NXT

    cudaFuncSetAttribute(mmagemm, cudaFuncAttributeMaxDynamicSharedMemorySize, 81920);

    spectral_kernel<<<NBS, 256>>>(WA, WB, WC);
    splitk<<<32768,256>>>(x, Xh, Xl, -1);
    splitk<<<1024,256>>>(WA, WA_h, WA_l, 0);
    splitk<<<1024,256>>>(WB, WB_h, WB_l, 1);
    splitk<<<1024,256>>>(WC, WC_h, WC_l, 2);
    // xb = x*(WB/s)^T, scan layout; chunk-0 slice also in bf16
    mmagemm<<<dim3(8,256),256,81920>>>(Xh,Xl, WB_h,WB_l, nullptr, xb, XB0h,XB0l, nullptr,nullptr, 1,0);
    tsplit<<<dim3(32,32), dim3(32,8)>>>(WA, PTh, PTl, 0);   // PT = (A/s)^T
    // ladder: P_r = A^(2^r), r=1..9; each = GEMM + transpose-split
    for (int r=1;r<=9;r++) {
        mmagemm<<<dim3(8,8),256,81920>>>(Ph[r-1],Pl[r-1], PTh,PTl, nullptr, Pf, Ph[r],Pl[r], nullptr,nullptr, 0,0);
        tsplit<<<dim3(32,32), dim3(32,8)>>>(Pf, PTh, PTl, -1);
    }
    zero3<<<128,256>>>(Tf, Th, Tl, 32768);  // chunk 0 of T = 0
    // pass 1: local scans (15 steps, M=2048); final step writes l_k into T at chunk k+1
    __nv_bfloat16 *ph_=XB0h, *pl_=XB0l;
    for (int j = 1; j < 16; j++) {
        __nv_bfloat16 *dh = (j==15)?(Th+32768):((j&1)?S1h:S0h);
        __nv_bfloat16 *dl = (j==15)?(Tl+32768):((j&1)?S1l:S0l);
        mmagemm<<<dim3(8,16),256,81920>>>(ph_,pl_, WA_h,WA_l, xb+(size_t)j*2097152UL,
            (j==15)?(Tf+32768):nullptr, dh,dl, nullptr,nullptr, 0,0);
        ph_=dh; pl_=dl;
    }
    // Kogge-Stone over 64 chunks: 6 rounds, T/U ping-pong, padded buffers (96 chunks)
    float *cf=Tf, *of=Uf; __nv_bfloat16 *chh=Th,*cll=Tl,*ohh=Uh,*oll=Ul;
    for (int r=0;r<6;r++) {
        int d = 1<<r, n = d*32768;
        copy3<<<n/256,256>>>(of, ohh, oll, cf, chh, cll, n);
        mmagemm<<<dim3(8,16),256,81920>>>(chh,cll, Ph[4+r],Pl[4+r],
            cf+(size_t)n, of+(size_t)n, ohh+(size_t)n, oll+(size_t)n, nullptr,nullptr, 0,0);
        float* tf=cf; cf=of; of=tf;
        __nv_bfloat16 *t1=chh; chh=ohh; ohh=t1;
        __nv_bfloat16 *t2=cll; cll=oll; oll=t2;
    }
    // pass 3: rescan with true inits c_k (= chh/cll), scatter hs
    ph_=chh; pl_=cll;
    for (int j = 0; j < 16; j++) {
        __nv_bfloat16 *dh = (j&1)?S1h:S0h, *dl = (j&1)?S1l:S0l;
        mmagemm<<<dim3(8,16),256,81920>>>(ph_,pl_, WA_h,WA_l, xb+(size_t)j*2097152UL,
            hs, dh,dl, HSh,HSl, 2,j);
        ph_=dh; pl_=dl;
    }
    mmagemm<<<dim3(8,256),256,81920>>>(HSh,HSl, WC_h,WC_l, nullptr, ys, nullptr,nullptr, nullptr,nullptr, 0,0);
    (void)in_sizes; (void)n_in; (void)out_size;
}

// round 13
// speedup vs baseline: 3.3909x; 1.1171x over previous
#include <cuda_runtime.h>
#include <cuda_bf16.h>
#include <cstdint>
#include <math.h>
#define HD 1024
#define NBS 64
#define F_XB 0UL
#define F_PF (F_XB+33554432UL)
#define F_T  (F_PF+1048576UL)
#define F_U  (F_T+3145728UL)
#define F_TOT (F_U+3145728UL)
__device__ float g_f[F_TOT];
__device__ __nv_bfloat16 g_b[188743680UL];
__device__ float sp_part3[3*NBS*HD];
__device__ float sp_u3[3*HD], sp_v3[3*HD], sp_w3[3*HD];
__device__ float sp_scale[6];     // [g]=1/||u||, [3+g]=1/||v||
__device__ float d_rsigma[3];
__device__ unsigned bar_c3[3] = {0,0,0}, bar_g3[3] = {0,0,0};

__device__ __forceinline__ void gbar3(int g) {
    __syncthreads(); __threadfence();
    if (threadIdx.x == 0) {
        unsigned gen = atomicAdd(&bar_g3[g], 0u);
        if (atomicAdd(&bar_c3[g], 1u) == NBS - 1u) {
            bar_c3[g] = 0u; __threadfence(); atomicExch(&bar_g3[g], gen + 1u);
        } else while (atomicAdd(&bar_g3[g], 0u) == gen) __nanosleep(64);
    }
    __syncthreads();
}

// all 3 power iterations in parallel: group g = bid/64 handles matrix g.
__global__ void __launch_bounds__(256) spectral3(const float* __restrict__ WA,
    const float* __restrict__ WB, const float* __restrict__ WC) {
    __shared__ float red[256];
    const int tid = threadIdx.x, g = blockIdx.x >> 6, lb = blockIdx.x & 63;
    const int gtid = lb*256 + tid;
    const float* W = (g==0) ? WA : ((g==1) ? WB : WC);
    float* up = sp_u3 + g*HD;
    float* vp = sp_v3 + g*HD;
    float* wp = sp_w3 + g*HD;
    float* part = sp_part3 + (size_t)g*NBS*HD;
    if (gtid < HD) up[gtid] = 0.03125f;
    if (gtid == 0) sp_scale[g] = 1.f;
    gbar3(g);
    for (int it = 0; it <= 10; it++) {
        { // partial of W^T u_raw over 16 rows
            const int i0 = lb*16;
            float a0=0,a1=0,a2=0,a3=0;
            for (int i = i0; i < i0+16; i++) {
                float ui = __ldcg(&up[i]);
                const float* Wr = W + (size_t)i*HD;
                a0 += Wr[tid]*ui; a1 += Wr[tid+256]*ui;
                a2 += Wr[tid+512]*ui; a3 += Wr[tid+768]*ui;
            }
            part[lb*HD+tid]=a0; part[lb*HD+tid+256]=a1;
            part[lb*HD+tid+512]=a2; part[lb*HD+tid+768]=a3;
        }
        gbar3(g);
        if (gtid < HD) {
            float s=0;
            for (int b=0;b<NBS;b++) s += __ldcg(&part[b*HD+gtid]);
            vp[gtid] = s * __ldcg(&sp_scale[g]);   // v_raw = W^T (u_raw/||u_raw||)
        }
        gbar3(g);
        if (lb == 0) {
            float s=0;
            #pragma unroll
            for (int q=0;q<4;q++){ float x=__ldcg(&vp[tid*4+q]); s+=x*x; }
            red[tid]=s; __syncthreads();
            for (int st=128;st>0;st>>=1){ if(tid<st) red[tid]+=red[tid+st]; __syncthreads(); }
            if (tid==0) sp_scale[3+g] = 1.f/(sqrtf(red[0]) + 1e-12f);
        }
        gbar3(g);
        if (it == 10) break;
        { // u_raw = (W v_raw) * sv
            float sv = __ldcg(&sp_scale[3+g]);
            const int warp = gtid>>5, lane = gtid&31;
            for (int i = warp; i < HD; i += (NBS*256)/32) {
                const float* Wr = W + (size_t)i*HD;
                float s=0;
                for (int j=lane;j<HD;j+=32) s += Wr[j]*__ldcg(&vp[j]);
                #pragma unroll
                for (int o=16;o;o>>=1) s += __shfl_xor_sync(0xffffffffu,s,o);
                if (lane==0) up[i] = s*sv;
            }
        }
        gbar3(g);
        if (lb == 0) {
            float s=0;
            #pragma unroll
            for (int q=0;q<4;q++){ float x=__ldcg(&up[tid*4+q]); s+=x*x; }
            red[tid]=s; __syncthreads();
            for (int st=128;st>0;st>>=1){ if(tid<st) red[tid]+=red[tid+st]; __syncthreads(); }
            if (tid==0) sp_scale[g] = 1.f/(sqrtf(red[0]) + 1e-12f);
        }
        gbar3(g);
    }
    { // w = W v_hat
        float sv = __ldcg(&sp_scale[3+g]);
        const int warp = gtid>>5, lane = gtid&31;
        for (int i = warp; i < HD; i += (NBS*256)/32) {
            const float* Wr = W + (size_t)i*HD;
            float s=0;
            for (int j=lane;j<HD;j+=32) s += Wr[j]*__ldcg(&vp[j]);
            #pragma unroll
            for (int o=16;o;o>>=1) s += __shfl_xor_sync(0xffffffffu,s,o);
            if (lane==0) wp[i] = s*sv;
        }
    }
    gbar3(g);
    if (lb == 0) {
        float su = __ldcg(&sp_scale[g]);
        float s=0;
        #pragma unroll
        for (int q=0;q<4;q++) s += __ldcg(&up[tid*4+q])*su*__ldcg(&wp[tid*4+q]);
        red[tid]=s; __syncthreads();
        for (int st=128;st>0;st>>=1){ if(tid<st) red[tid]+=red[tid+st]; __syncthreads(); }
        if (tid==0) d_rsigma[g] = 1.f/red[0];
    }
}

__device__ __forceinline__ void split1(float v, __nv_bfloat16& h, __nv_bfloat16& l) {
    h = __float2bfloat16_rn(v);
    l = __float2bfloat16_rn(v - __bfloat162float(h));
}
__device__ __forceinline__ uint32_t s2u(const void* p) {
    uint32_t a;
    asm("{.reg .u64 t; cvta.to.shared.u64 t, %1; cvt.u32.u64 %0, t;}" : "=r"(a) : "l"(p));
    return a;
}
#define CP16(d,s) asm volatile("cp.async.cg.shared.global [%0], [%1], 16;" :: "r"(d), "l"(s))
#define CPC() asm volatile("cp.async.commit_group;")
#define CPW1() asm volatile("cp.async.wait_group 1;")
#define CPW0() asm volatile("cp.async.wait_group 0;")
#define LDSM4(r0,r1,r2,r3,a) asm volatile("ldmatrix.sync.aligned.m8n8.x4.shared.b16 {%0,%1,%2,%3}, [%4];" \
    : "=r"(r0),"=r"(r1),"=r"(r2),"=r"(r3) : "r"(a))
#define MMA(d,a,b0,b1) asm volatile( \
    "mma.sync.aligned.m16n8k16.row.col.f32.bf16.bf16.f32 {%0,%1,%2,%3},{%4,%5,%6,%7},{%8,%9},{%0,%1,%2,%3};" \
    : "+f"(d[0]),"+f"(d[1]),"+f"(d[2]),"+f"(d[3]) \
    : "r"(a[0]),"r"(a[1]),"r"(a[2]),"r"(a[3]),"r"(b0),"r"(b1))

__global__ void splitk(const float* __restrict__ src, __nv_bfloat16* __restrict__ oh,
                       __nv_bfloat16* __restrict__ ol, int sidx) {
    float f = sidx >= 0 ? d_rsigma[sidx] : 1.f;
    size_t i = ((size_t)blockIdx.x*256 + threadIdx.x)*4;
    float4 v = *(const float4*)(src + i);
    __nv_bfloat16 h0,l0,h1,l1,h2,l2,h3,l3;
    split1(v.x*f,h0,l0); split1(v.y*f,h1,l1); split1(v.z*f,h2,l2); split1(v.w*f,h3,l3);
    __nv_bfloat162 a,b;
    a.x=h0;a.y=h1;b.x=h2;b.y=h3;
    *(__nv_bfloat162*)(oh+i)=a; *(__nv_bfloat162*)(oh+i+2)=b;
    a.x=l0;a.y=l1;b.x=l2;b.y=l3;
    *(__nv_bfloat162*)(ol+i)=a; *(__nv_bfloat162*)(ol+i+2)=b;
}

__global__ void tsplit(const float* __restrict__ W, __nv_bfloat16* __restrict__ oh,
                       __nv_bfloat16* __restrict__ ol, int sidx) {
    __shared__ float t[32][33];
    float s = sidx >= 0 ? d_rsigma[sidx] : 1.f;
    int x = blockIdx.x*32 + threadIdx.x, y0 = blockIdx.y*32;
    #pragma unroll
    for (int i = threadIdx.y; i < 32; i += 8)
        t[i][threadIdx.x] = W[(size_t)(y0+i)*HD + x];
    __syncthreads();
    int ox = y0 + threadIdx.x, oy0 = blockIdx.x*32;
    #pragma unroll
    for (int i = threadIdx.y; i < 32; i += 8) {
        __nv_bfloat16 h,l; split1(t[threadIdx.x][i]*s,h,l);
        oh[(size_t)(oy0+i)*HD + ox] = h;
        ol[(size_t)(oy0+i)*HD + ox] = l;
    }
}

#define STR 40
// R6-proven mainloop + term-major MMA reorder (same-acc reuse distance 1 -> 4).
// Stage layout per 40960B: Ah+0, Al+10240, Bh+20480, Bl+30720.
// mode 0: Cf?/Oh? at r. mode 1: xb scatter (CHUNK=16; bf16 if row<2048). mode 2: pass3.
__global__ void __launch_bounds__(256,2) mmagemm(
    const __nv_bfloat16* __restrict__ Ahh, const __nv_bfloat16* __restrict__ All,
    const __nv_bfloat16* __restrict__ Bhh, const __nv_bfloat16* __restrict__ Bll,
    const float* __restrict__ Add, float* __restrict__ Cf,
    __nv_bfloat16* __restrict__ Oh, __nv_bfloat16* __restrict__ Ol,
    __nv_bfloat16* __restrict__ O2h, __nv_bfloat16* __restrict__ O2l,
    int mode, int jp)
{
    extern __shared__ __nv_bfloat16 smx[];
    const int tid=threadIdx.x, lane=tid&31, wid=tid>>5, wm=wid&3, wn=wid>>2;
    const int m0=blockIdx.y*128, n0=blockIdx.x*128;
    const uint32_t sb=s2u(smx);
    const __nv_bfloat16* srcs[4]={Ahh,All,Bhh,Bll};
    float acc[2][8][4];
    #pragma unroll
    for (int i=0;i<2;i++)
        #pragma unroll
        for (int j=0;j<8;j++)
            #pragma unroll
            for (int q=0;q<4;q++) acc[i][j][q]=0.f;
    const int lr=tid>>1, lc=(tid&1)*16;
    auto ldst = [&](int kt, int st){
        const int k0 = kt*32;
        #pragma unroll
        for (int a=0;a<4;a++) {
            int row = (a<2 ? m0 : n0) + lr;
            const char* s = (const char*)(srcs[a] + (size_t)row*1024 + k0 + lc);
            uint32_t d = sb + (uint32_t)(st*40960 + a*10240 + (lr*STR+lc)*2);
            CP16(d, s); CP16(d+16, s+16);
        }
    };
    ldst(0,0); CPC();
    for (int kt=0; kt<32; kt++) {
        if (kt<31) { ldst(kt+1,(kt+1)&1); CPC(); CPW1(); } else CPW0();
        __syncthreads();
        const uint32_t ab = sb + (kt&1)*40960;
        #pragma unroll
        for (int kh=0;kh<2;kh++) {
            uint32_t ah[2][4], al[2][4];
            #pragma unroll
            for (int ti=0;ti<2;ti++) {
                uint32_t ad = ab + (uint32_t)(((wm*32+ti*16+(lane&15))*STR + kh*16+(lane>>4)*8)*2);
                LDSM4(ah[ti][0],ah[ti][1],ah[ti][2],ah[ti][3], ad);
                LDSM4(al[ti][0],al[ti][1],al[ti][2],al[ti][3], ad+10240);
            }
            #pragma unroll
            for (int q=0;q<4;q++) {
                uint32_t bd = ab + 20480u + (uint32_t)(((wn*64+q*16+(lane&7)+((lane>>4)&1)*8)*STR + kh*16+((lane>>3)&1)*8)*2);
                uint32_t h0,h1,h2,h3,l0,l1,l2,l3;
                LDSM4(h0,h1,h2,h3, bd);
                LDSM4(l0,l1,l2,l3, bd+10240);
                // term-major: same accumulator re-touched only every 4 MMAs
                #pragma unroll
                for (int ti=0;ti<2;ti++) {
                    MMA(acc[ti][q*2],   ah[ti], h0,h1);
                    MMA(acc[ti][q*2+1], ah[ti], h2,h3);
                }
                #pragma unroll
                for (int ti=0;ti<2;ti++) {
                    MMA(acc[ti][q*2],   ah[ti], l0,l1);
                    MMA(acc[ti][q*2+1], ah[ti], l2,l3);
                }
                #pragma unroll
                for (int ti=0;ti<2;ti++) {
                    MMA(acc[ti][q*2],   al[ti], h0,h1);
                    MMA(acc[ti][q*2+1], al[ti], h2,h3);
                }
            }
        }
        __syncthreads();
    }
    const int rb0 = m0 + wm*32 + (lane>>2);
    #pragma unroll
    for (int ti=0;ti<2;ti++)
    #pragma unroll
    for (int j=0;j<8;j++)
    #pragma unroll
    for (int hf=0;hf<2;hf++) {
        int r = rb0 + ti*16 + hf*8;
        int c = n0 + wn*64 + j*8 + (lane&3)*2;
        float v0=acc[ti][j][hf*2], v1=acc[ti][j][hf*2+1];
        if (Add) { float2 ad = *(const float2*)(Add+(size_t)r*1024+c); v0+=ad.x; v1+=ad.y; }
        __nv_bfloat16 h0,l0,h1,l1; split1(v0,h0,l0); split1(v1,h1,l1);
        __nv_bfloat162 ph,pl; ph.x=h0;ph.y=h1; pl.x=l0;pl.y=l1;
        if (mode==2) {
            *(__nv_bfloat162*)(Oh+(size_t)r*1024+c)=ph;
            *(__nv_bfloat162*)(Ol+(size_t)r*1024+c)=pl;
            int k=r>>5, b_=r&31;
            size_t o2=(size_t)b_*1024+(size_t)k*16+jp;
            *(float2*)(Cf+o2*1024+c)=make_float2(v0,v1);
            *(__nv_bfloat162*)(O2h+o2*1024+c)=ph;
            *(__nv_bfloat162*)(O2l+o2*1024+c)=pl;
        } else {
            size_t orow=(size_t)r;
            if (mode==1){ int b_=r>>10,t=r&1023,k=t>>4,jj=t&15; orow=(size_t)((((jj<<6)|k)<<5)|b_); }
            if (Cf) *(float2*)(Cf+orow*1024+c)=make_float2(v0,v1);
            if (Oh && (mode!=1 || orow<2048)) {
                *(__nv_bfloat162*)(Oh+orow*1024+c)=ph;
                *(__nv_bfloat162*)(Ol+orow*1024+c)=pl;
            }
        }
    }
}

__global__ void copy3(float* df, __nv_bfloat16* dh, __nv_bfloat16* dl,
    const float* sf, const __nv_bfloat16* sh, const __nv_bfloat16* sl, int n) {
    int i = blockIdx.x*256 + threadIdx.x;
    if (i < n) { df[i]=sf[i]; dh[i]=sh[i]; dl[i]=sl[i]; }
}
__global__ void zero3(float* f, __nv_bfloat16* h, __nv_bfloat16* l, int n) {
    int i = blockIdx.x*256 + threadIdx.x;
    if (i < n) { f[i]=0.f; h[i]=__float2bfloat16(0.f); l[i]=__float2bfloat16(0.f); }
}

extern "C" void kernel_launch(void* const* d_in, const int* in_sizes, int n_in,
                              void* d_out, int out_size) {
    const float* x  = (const float*)d_in[0];
    const float* WA = (const float*)d_in[1];
    const float* WB = (const float*)d_in[2];
    const float* WC = (const float*)d_in[3];
    float* ys = (float*)d_out;
    float* hs = ys + 33554432UL;
    float* F = nullptr; cudaGetSymbolAddress((void**)&F, g_f);
    __nv_bfloat16* G = nullptr; cudaGetSymbolAddress((void**)&G, g_b);
    float *xb=F+F_XB, *Pf=F+F_PF, *Tf=F+F_T, *Uf=F+F_U;
    __nv_bfloat16* p = G;
    #define NXT(nm,sz) __nv_bfloat16 *nm##h=p, *nm##l=p+(sz); p += 2UL*(sz);
    NXT(X,33554432UL) NXT(WA_,1048576UL) NXT(WAT,1048576UL) NXT(WB_,1048576UL)
    NXT(WC_,1048576UL)
    __nv_bfloat16 *Ph[10], *Pl[10];
    Ph[0]=WA_h; Pl[0]=WA_l;
    for (int r=1;r<=9;r++){ Ph[r]=p; Pl[r]=p+1048576UL; p+=2097152UL; }
    NXT(PT,1048576UL)
    NXT(XB0,2097152UL) NXT(S0,2097152UL) NXT(S1,2097152UL)
    __nv_bfloat16 *Th=p, *Tl=p+3145728UL; p+=6291456UL;
    __nv_bfloat16 *Uh=p, *Ul=p+3145728UL; p+=6291456UL;
    NXT(HS,33554432UL)
    #undef NXT

    cudaFuncSetAttribute(mmagemm, cudaFuncAttributeMaxDynamicSharedMemorySize, 81920);

    spectral3<<<192, 256>>>(WA, WB, WC);
    splitk<<<32768,256>>>(x, Xh, Xl, -1);
    splitk<<<1024,256>>>(WA, WA_h, WA_l, 0);
    splitk<<<1024,256>>>(WB, WB_h, WB_l, 1);
    splitk<<<1024,256>>>(WC, WC_h, WC_l, 2);
    // xb = x*(WB/s)^T, scan layout; chunk-0 slice also in bf16
    mmagemm<<<dim3(8,256),256,81920>>>(Xh,Xl, WB_h,WB_l, nullptr, xb, XB0h,XB0l, nullptr,nullptr, 1,0);
    tsplit<<<dim3(32,32), dim3(32,8)>>>(WA, PTh, PTl, 0);   // PT = (A/s)^T
    // ladder: P_r = A^(2^r), r=1..9; each = GEMM + transpose-split
    for (int r=1;r<=9;r++) {
        mmagemm<<<dim3(8,8),256,81920>>>(Ph[r-1],Pl[r-1], PTh,PTl, nullptr, Pf, Ph[r],Pl[r], nullptr,nullptr, 0,0);
        tsplit<<<dim3(32,32), dim3(32,8)>>>(Pf, PTh, PTl, -1);
    }
    zero3<<<128,256>>>(Tf, Th, Tl, 32768);  // chunk 0 of T = 0
    // pass 1: local scans (15 steps, M=2048); final step writes l_k into T at chunk k+1
    __nv_bfloat16 *ph_=XB0h, *pl_=XB0l;
    for (int j = 1; j < 16; j++) {
        __nv_bfloat16 *dh = (j==15)?(Th+32768):((j&1)?S1h:S0h);
        __nv_bfloat16 *dl = (j==15)?(Tl+32768):((j&1)?S1l:S0l);
        mmagemm<<<dim3(8,16),256,81920>>>(ph_,pl_, WA_h,WA_l, xb+(size_t)j*2097152UL,
            (j==15)?(Tf+32768):nullptr, dh,dl, nullptr,nullptr, 0,0);
        ph_=dh; pl_=dl;
    }
    // Kogge-Stone over 64 chunks: 6 rounds, T/U ping-pong, padded buffers (96 chunks)
    float *cf=Tf, *of=Uf; __nv_bfloat16 *chh=Th,*cll=Tl,*ohh=Uh,*oll=Ul;
    for (int r=0;r<6;r++) {
        int d = 1<<r, n = d*32768;
        copy3<<<n/256,256>>>(of, ohh, oll, cf, chh, cll, n);
        mmagemm<<<dim3(8,16),256,81920>>>(chh,cll, Ph[4+r],Pl[4+r],
            cf+(size_t)n, of+(size_t)n, ohh+(size_t)n, oll+(size_t)n, nullptr,nullptr, 0,0);
        float* tf=cf; cf=of; of=tf;
        __nv_bfloat16 *t1=chh; chh=ohh; ohh=t1;
        __nv_bfloat16 *t2=cll; cll=oll; oll=t2;
    }
    // pass 3: rescan with true inits c_k, scatter hs
    ph_=chh; pl_=cll;
    for (int j = 0; j < 16; j++) {
        __nv_bfloat16 *dh = (j&1)?S1h:S0h, *dl = (j&1)?S1l:S0l;
        mmagemm<<<dim3(8,16),256,81920>>>(ph_,pl_, WA_h,WA_l, xb+(size_t)j*2097152UL,
            hs, dh,dl, HSh,HSl, 2,j);
        ph_=dh; pl_=dl;
    }
    mmagemm<<<dim3(8,256),256,81920>>>(HSh,HSl, WC_h,WC_l, nullptr, ys, nullptr,nullptr, nullptr,nullptr, 0,0);
    (void)in_sizes; (void)n_in; (void)out_size;
}

// round 14
// speedup vs baseline: 3.5559x; 1.0487x over previous
#include <cuda_runtime.h>
#include <cuda_bf16.h>
#include <cstdint>
#include <math.h>
#define HD 1024
#define NBS 64
#define F_XB 0UL
#define F_PF (F_XB+33554432UL)
#define F_T  (F_PF+1048576UL)
#define F_U  (F_T+6291456UL)
#define F_TOT (F_U+6291456UL)
__device__ float g_f[F_TOT];
__device__ __nv_bfloat16 g_b[213909504UL];
__device__ float sp_part3[3*NBS*HD];
__device__ float sp_u3[3*HD], sp_v3[3*HD], sp_w3[3*HD];
__device__ float sp_scale[6];
__device__ float d_rsigma[3];
__device__ unsigned bar_c3[3] = {0,0,0}, bar_g3[3] = {0,0,0};

__device__ __forceinline__ void gbar3(int g) {
    __syncthreads(); __threadfence();
    if (threadIdx.x == 0) {
        unsigned gen = atomicAdd(&bar_g3[g], 0u);
        if (atomicAdd(&bar_c3[g], 1u) == NBS - 1u) {
            bar_c3[g] = 0u; __threadfence(); atomicExch(&bar_g3[g], gen + 1u);
        } else while (atomicAdd(&bar_g3[g], 0u) == gen) __nanosleep(64);
    }
    __syncthreads();
}

__global__ void __launch_bounds__(256) spectral3(const float* __restrict__ WA,
    const float* __restrict__ WB, const float* __restrict__ WC) {
    __shared__ float red[256];
    const int tid = threadIdx.x, g = blockIdx.x >> 6, lb = blockIdx.x & 63;
    const int gtid = lb*256 + tid;
    const float* W = (g==0) ? WA : ((g==1) ? WB : WC);
    float* up = sp_u3 + g*HD;
    float* vp = sp_v3 + g*HD;
    float* wp = sp_w3 + g*HD;
    float* part = sp_part3 + (size_t)g*NBS*HD;
    if (gtid < HD) up[gtid] = 0.03125f;
    if (gtid == 0) sp_scale[g] = 1.f;
    gbar3(g);
    for (int it = 0; it <= 10; it++) {
        {
            const int i0 = lb*16;
            float a0=0,a1=0,a2=0,a3=0;
            for (int i = i0; i < i0+16; i++) {
                float ui = __ldcg(&up[i]);
                const float* Wr = W + (size_t)i*HD;
                a0 += Wr[tid]*ui; a1 += Wr[tid+256]*ui;
                a2 += Wr[tid+512]*ui; a3 += Wr[tid+768]*ui;
            }
            part[lb*HD+tid]=a0; part[lb*HD+tid+256]=a1;
            part[lb*HD+tid+512]=a2; part[lb*HD+tid+768]=a3;
        }
        gbar3(g);
        if (gtid < HD) {
            float s=0;
            for (int b=0;b<NBS;b++) s += __ldcg(&part[b*HD+gtid]);
            vp[gtid] = s * __ldcg(&sp_scale[g]);
        }
        gbar3(g);
        if (lb == 0) {
            float s=0;
            #pragma unroll
            for (int q=0;q<4;q++){ float x=__ldcg(&vp[tid*4+q]); s+=x*x; }
            red[tid]=s; __syncthreads();
            for (int st=128;st>0;st>>=1){ if(tid<st) red[tid]+=red[tid+st]; __syncthreads(); }
            if (tid==0) sp_scale[3+g] = 1.f/(sqrtf(red[0]) + 1e-12f);
        }
        gbar3(g);
        if (it == 10) break;
        {
            float sv = __ldcg(&sp_scale[3+g]);
            const int warp = gtid>>5, lane = gtid&31;
            for (int i = warp; i < HD; i += (NBS*256)/32) {
                const float* Wr = W + (size_t)i*HD;
                float s=0;
                for (int j=lane;j<HD;j+=32) s += Wr[j]*__ldcg(&vp[j]);
                #pragma unroll
                for (int o=16;o;o>>=1) s += __shfl_xor_sync(0xffffffffu,s,o);
                if (lane==0) up[i] = s*sv;
            }
        }
        gbar3(g);
        if (lb == 0) {
            float s=0;
            #pragma unroll
            for (int q=0;q<4;q++){ float x=__ldcg(&up[tid*4+q]); s+=x*x; }
            red[tid]=s; __syncthreads();
            for (int st=128;st>0;st>>=1){ if(tid<st) red[tid]+=red[tid+st]; __syncthreads(); }
            if (tid==0) sp_scale[g] = 1.f/(sqrtf(red[0]) + 1e-12f);
        }
        gbar3(g);
    }
    {
        float sv = __ldcg(&sp_scale[3+g]);
        const int warp = gtid>>5, lane = gtid&31;
        for (int i = warp; i < HD; i += (NBS*256)/32) {
            const float* Wr = W + (size_t)i*HD;
            float s=0;
            for (int j=lane;j<HD;j+=32) s += Wr[j]*__ldcg(&vp[j]);
            #pragma unroll
            for (int o=16;o;o>>=1) s += __shfl_xor_sync(0xffffffffu,s,o);
            if (lane==0) wp[i] = s*sv;
        }
    }
    gbar3(g);
    if (lb == 0) {
        float su = __ldcg(&sp_scale[g]);
        float s=0;
        #pragma unroll
        for (int q=0;q<4;q++) s += __ldcg(&up[tid*4+q])*su*__ldcg(&wp[tid*4+q]);
        red[tid]=s; __syncthreads();
        for (int st=128;st>0;st>>=1){ if(tid<st) red[tid]+=red[tid+st]; __syncthreads(); }
        if (tid==0) d_rsigma[g] = 1.f/red[0];
    }
}

__device__ __forceinline__ void split1(float v, __nv_bfloat16& h, __nv_bfloat16& l) {
    h = __float2bfloat16_rn(v);
    l = __float2bfloat16_rn(v - __bfloat162float(h));
}
__device__ __forceinline__ uint32_t s2u(const void* p) {
    uint32_t a;
    asm("{.reg .u64 t; cvta.to.shared.u64 t, %1; cvt.u32.u64 %0, t;}" : "=r"(a) : "l"(p));
    return a;
}
#define CP16(d,s) asm volatile("cp.async.cg.shared.global [%0], [%1], 16;" :: "r"(d), "l"(s))
#define CPC() asm volatile("cp.async.commit_group;")
#define CPW1() asm volatile("cp.async.wait_group 1;")
#define CPW0() asm volatile("cp.async.wait_group 0;")
#define LDSM4(r0,r1,r2,r3,a) asm volatile("ldmatrix.sync.aligned.m8n8.x4.shared.b16 {%0,%1,%2,%3}, [%4];" \
    : "=r"(r0),"=r"(r1),"=r"(r2),"=r"(r3) : "r"(a))
#define MMA(d,a,b0,b1) asm volatile( \
    "mma.sync.aligned.m16n8k16.row.col.f32.bf16.bf16.f32 {%0,%1,%2,%3},{%4,%5,%6,%7},{%8,%9},{%0,%1,%2,%3};" \
    : "+f"(d[0]),"+f"(d[1]),"+f"(d[2]),"+f"(d[3]) \
    : "r"(a[0]),"r"(a[1]),"r"(a[2]),"r"(a[3]),"r"(b0),"r"(b1))

__global__ void splitk(const float* __restrict__ src, __nv_bfloat16* __restrict__ oh,
                       __nv_bfloat16* __restrict__ ol, int sidx) {
    float f = sidx >= 0 ? d_rsigma[sidx] : 1.f;
    size_t i = ((size_t)blockIdx.x*256 + threadIdx.x)*4;
    float4 v = *(const float4*)(src + i);
    __nv_bfloat16 h0,l0,h1,l1,h2,l2,h3,l3;
    split1(v.x*f,h0,l0); split1(v.y*f,h1,l1); split1(v.z*f,h2,l2); split1(v.w*f,h3,l3);
    __nv_bfloat162 a,b;
    a.x=h0;a.y=h1;b.x=h2;b.y=h3;
    *(__nv_bfloat162*)(oh+i)=a; *(__nv_bfloat162*)(oh+i+2)=b;
    a.x=l0;a.y=l1;b.x=l2;b.y=l3;
    *(__nv_bfloat162*)(ol+i)=a; *(__nv_bfloat162*)(ol+i+2)=b;
}

__global__ void tsplit(const float* __restrict__ W, __nv_bfloat16* __restrict__ oh,
                       __nv_bfloat16* __restrict__ ol, int sidx) {
    __shared__ float t[32][33];
    float s = sidx >= 0 ? d_rsigma[sidx] : 1.f;
    int x = blockIdx.x*32 + threadIdx.x, y0 = blockIdx.y*32;
    #pragma unroll
    for (int i = threadIdx.y; i < 32; i += 8)
        t[i][threadIdx.x] = W[(size_t)(y0+i)*HD + x];
    __syncthreads();
    int ox = y0 + threadIdx.x, oy0 = blockIdx.x*32;
    #pragma unroll
    for (int i = threadIdx.y; i < 32; i += 8) {
        __nv_bfloat16 h,l; split1(t[threadIdx.x][i]*s,h,l);
        oh[(size_t)(oy0+i)*HD + ox] = h;
        ol[(size_t)(oy0+i)*HD + ox] = l;
    }
}

#define STR 40
// R12-winning mainloop (term-major MMA order). CHUNK=8 epilogue mappings.
// mode 0: Cf?/Oh? at r. mode 1: xb scatter (bf16 if scan row<4096). mode 2: pass3 hs.
__global__ void __launch_bounds__(256,2) mmagemm(
    const __nv_bfloat16* __restrict__ Ahh, const __nv_bfloat16* __restrict__ All,
    const __nv_bfloat16* __restrict__ Bhh, const __nv_bfloat16* __restrict__ Bll,
    const float* __restrict__ Add, float* __restrict__ Cf,
    __nv_bfloat16* __restrict__ Oh, __nv_bfloat16* __restrict__ Ol,
    __nv_bfloat16* __restrict__ O2h, __nv_bfloat16* __restrict__ O2l,
    int mode, int jp)
{
    extern __shared__ __nv_bfloat16 smx[];
    const int tid=threadIdx.x, lane=tid&31, wid=tid>>5, wm=wid&3, wn=wid>>2;
    const int m0=blockIdx.y*128, n0=blockIdx.x*128;
    const uint32_t sb=s2u(smx);
    const __nv_bfloat16* srcs[4]={Ahh,All,Bhh,Bll};
    float acc[2][8][4];
    #pragma unroll
    for (int i=0;i<2;i++)
        #pragma unroll
        for (int j=0;j<8;j++)
            #pragma unroll
            for (int q=0;q<4;q++) acc[i][j][q]=0.f;
    const int lr=tid>>1, lc=(tid&1)*16;
    auto ldst = [&](int kt, int st){
        const int k0 = kt*32;
        #pragma unroll
        for (int a=0;a<4;a++) {
            int row = (a<2 ? m0 : n0) + lr;
            const char* s = (const char*)(srcs[a] + (size_t)row*1024 + k0 + lc);
            uint32_t d = sb + (uint32_t)(st*40960 + a*10240 + (lr*STR+lc)*2);
            CP16(d, s); CP16(d+16, s+16);
        }
    };
    ldst(0,0); CPC();
    for (int kt=0; kt<32; kt++) {
        if (kt<31) { ldst(kt+1,(kt+1)&1); CPC(); CPW1(); } else CPW0();
        __syncthreads();
        const uint32_t ab = sb + (kt&1)*40960;
        #pragma unroll
        for (int kh=0;kh<2;kh++) {
            uint32_t ah[2][4], al[2][4];
            #pragma unroll
            for (int ti=0;ti<2;ti++) {
                uint32_t ad = ab + (uint32_t)(((wm*32+ti*16+(lane&15))*STR + kh*16+(lane>>4)*8)*2);
                LDSM4(ah[ti][0],ah[ti][1],ah[ti][2],ah[ti][3], ad);
                LDSM4(al[ti][0],al[ti][1],al[ti][2],al[ti][3], ad+10240);
            }
            #pragma unroll
            for (int q=0;q<4;q++) {
                uint32_t bd = ab + 20480u + (uint32_t)(((wn*64+q*16+(lane&7)+((lane>>4)&1)*8)*STR + kh*16+((lane>>3)&1)*8)*2);
                uint32_t h0,h1,h2,h3,l0,l1,l2,l3;
                LDSM4(h0,h1,h2,h3, bd);
                LDSM4(l0,l1,l2,l3, bd+10240);
                #pragma unroll
                for (int ti=0;ti<2;ti++) {
                    MMA(acc[ti][q*2],   ah[ti], h0,h1);
                    MMA(acc[ti][q*2+1], ah[ti], h2,h3);
                }
                #pragma unroll
                for (int ti=0;ti<2;ti++) {
                    MMA(acc[ti][q*2],   ah[ti], l0,l1);
                    MMA(acc[ti][q*2+1], ah[ti], l2,l3);
                }
                #pragma unroll
                for (int ti=0;ti<2;ti++) {
                    MMA(acc[ti][q*2],   al[ti], h0,h1);
                    MMA(acc[ti][q*2+1], al[ti], h2,h3);
                }
            }
        }
        __syncthreads();
    }
    const int rb0 = m0 + wm*32 + (lane>>2);
    #pragma unroll
    for (int ti=0;ti<2;ti++)
    #pragma unroll
    for (int j=0;j<8;j++)
    #pragma unroll
    for (int hf=0;hf<2;hf++) {
        int r = rb0 + ti*16 + hf*8;
        int c = n0 + wn*64 + j*8 + (lane&3)*2;
        float v0=acc[ti][j][hf*2], v1=acc[ti][j][hf*2+1];
        if (Add) { float2 ad = *(const float2*)(Add+(size_t)r*1024+c); v0+=ad.x; v1+=ad.y; }
        __nv_bfloat16 h0,l0,h1,l1; split1(v0,h0,l0); split1(v1,h1,l1);
        __nv_bfloat162 ph,pl; ph.x=h0;ph.y=h1; pl.x=l0;pl.y=l1;
        if (mode==2) {
            *(__nv_bfloat162*)(Oh+(size_t)r*1024+c)=ph;
            *(__nv_bfloat162*)(Ol+(size_t)r*1024+c)=pl;
            int k=r>>5, b_=r&31;
            size_t o2=(size_t)b_*1024+(size_t)k*8+jp;
            *(float2*)(Cf+o2*1024+c)=make_float2(v0,v1);
            *(__nv_bfloat162*)(O2h+o2*1024+c)=ph;
            *(__nv_bfloat162*)(O2l+o2*1024+c)=pl;
        } else {
            size_t orow=(size_t)r;
            if (mode==1){ int b_=r>>10,t=r&1023,k=t>>3,jj=t&7; orow=(size_t)((((jj<<7)|k)<<5)|b_); }
            if (Cf) *(float2*)(Cf+orow*1024+c)=make_float2(v0,v1);
            if (Oh && (mode!=1 || orow<4096)) {
                *(__nv_bfloat162*)(Oh+orow*1024+c)=ph;
                *(__nv_bfloat162*)(Ol+orow*1024+c)=pl;
            }
        }
    }
}

__global__ void copy3(float* df, __nv_bfloat16* dh, __nv_bfloat16* dl,
    const float* sf, const __nv_bfloat16* sh, const __nv_bfloat16* sl, int n) {
    int i = blockIdx.x*256 + threadIdx.x;
    if (i < n) { df[i]=sf[i]; dh[i]=sh[i]; dl[i]=sl[i]; }
}
__global__ void zero3(float* f, __nv_bfloat16* h, __nv_bfloat16* l, int n) {
    int i = blockIdx.x*256 + threadIdx.x;
    if (i < n) { f[i]=0.f; h[i]=__float2bfloat16(0.f); l[i]=__float2bfloat16(0.f); }
}

extern "C" void kernel_launch(void* const* d_in, const int* in_sizes, int n_in,
                              void* d_out, int out_size) {
    const float* x  = (const float*)d_in[0];
    const float* WA = (const float*)d_in[1];
    const float* WB = (const float*)d_in[2];
    const float* WC = (const float*)d_in[3];
    float* ys = (float*)d_out;
    float* hs = ys + 33554432UL;
    float* F = nullptr; cudaGetSymbolAddress((void**)&F, g_f);
    __nv_bfloat16* G = nullptr; cudaGetSymbolAddress((void**)&G, g_b);
    float *xb=F+F_XB, *Pf=F+F_PF, *Tf=F+F_T, *Uf=F+F_U;
    __nv_bfloat16* p = G;
    #define NXT(nm,sz) __nv_bfloat16 *nm##h=p, *nm##l=p+(sz); p += 2UL*(sz);
    NXT(X,33554432UL) NXT(WA_,1048576UL) NXT(WB_,1048576UL) NXT(WC_,1048576UL)
    __nv_bfloat16 *Ph[10], *Pl[10];
    Ph[0]=WA_h; Pl[0]=WA_l;
    for (int r=1;r<=9;r++){ Ph[r]=p; Pl[r]=p+1048576UL; p+=2097152UL; }
    NXT(PT,1048576UL)
    NXT(XB0,4194304UL) NXT(S0,4194304UL) NXT(S1,4194304UL)
    __nv_bfloat16 *Th=p, *Tl=p+6291456UL; p+=12582912UL;
    __nv_bfloat16 *Uh=p, *Ul=p+6291456UL; p+=12582912UL;
    NXT(HS,33554432UL)
    #undef NXT

    cudaFuncSetAttribute(mmagemm, cudaFuncAttributeMaxDynamicSharedMemorySize, 81920);

    spectral3<<<192, 256>>>(WA, WB, WC);
    splitk<<<32768,256>>>(x, Xh, Xl, -1);
    splitk<<<1024,256>>>(WA, WA_h, WA_l, 0);
    splitk<<<1024,256>>>(WB, WB_h, WB_l, 1);
    splitk<<<1024,256>>>(WC, WC_h, WC_l, 2);
    // xb = x*(WB/s)^T, CHUNK=8 scan layout; chunk-0 slice (4096 rows) also bf16
    mmagemm<<<dim3(8,256),256,81920>>>(Xh,Xl, WB_h,WB_l, nullptr, xb, XB0h,XB0l, nullptr,nullptr, 1,0);
    tsplit<<<dim3(32,32), dim3(32,8)>>>(WA, PTh, PTl, 0);
    // ladder: P_r = A^(2^r), r=1..9
    for (int r=1;r<=9;r++) {
        mmagemm<<<dim3(8,8),256,81920>>>(Ph[r-1],Pl[r-1], PTh,PTl, nullptr, Pf, Ph[r],Pl[r], nullptr,nullptr, 0,0);
        tsplit<<<dim3(32,32), dim3(32,8)>>>(Pf, PTh, PTl, -1);
    }
    zero3<<<128,256>>>(Tf, Th, Tl, 32768);  // chunk 0 of T = 0
    // pass 1: 7 local-scan steps (M=4096, 256 CTAs); last step -> T chunks 1..128
    __nv_bfloat16 *ph_=XB0h, *pl_=XB0l;
    for (int j = 1; j < 8; j++) {
        __nv_bfloat16 *dh = (j==7)?(Th+32768):((j&1)?S1h:S0h);
        __nv_bfloat16 *dl = (j==7)?(Tl+32768):((j&1)?S1l:S0l);
        mmagemm<<<dim3(8,32),256,81920>>>(ph_,pl_, WA_h,WA_l, xb+(size_t)j*4194304UL,
            (j==7)?(Tf+32768):nullptr, dh,dl, nullptr,nullptr, 0,0);
        ph_=dh; pl_=dl;
    }
    // Kogge-Stone over 128 chunks: 7 rounds, padded buffers (192 chunks)
    float *cf=Tf, *of=Uf; __nv_bfloat16 *chh=Th,*cll=Tl,*ohh=Uh,*oll=Ul;
    for (int r=0;r<7;r++) {
        int d = 1<<r, n = d*32768;
        copy3<<<(n+255)/256,256>>>(of, ohh, oll, cf, chh, cll, n);
        mmagemm<<<dim3(8,32),256,81920>>>(chh,cll, Ph[3+r],Pl[3+r],
            cf+(size_t)n, of+(size_t)n, ohh+(size_t)n, oll+(size_t)n, nullptr,nullptr, 0,0);
        float* tf=cf; cf=of; of=tf;
        __nv_bfloat16 *t1=chh; chh=ohh; ohh=t1;
        __nv_bfloat16 *t2=cll; cll=oll; oll=t2;
    }
    // pass 3: 8 rescan steps with true inits c_k (128 chunks, M=4096), scatter hs
    ph_=chh; pl_=cll;
    for (int j = 0; j < 8; j++) {
        __nv_bfloat16 *dh = (j&1)?S1h:S0h, *dl = (j&1)?S1l:S0l;
        mmagemm<<<dim3(8,32),256,81920>>>(ph_,pl_, WA_h,WA_l, xb+(size_t)j*4194304UL,
            hs, dh,dl, HSh,HSl, 2,j);
        ph_=dh; pl_=dl;
    }
    mmagemm<<<dim3(8,256),256,81920>>>(HSh,HSl, WC_h,WC_l, nullptr, ys, nullptr,nullptr, nullptr,nullptr, 0,0);
    (void)in_sizes; (void)n_in; (void)out_size;
}

// round 15
// speedup vs baseline: 3.5999x; 1.0124x over previous
#include <cuda_runtime.h>
#include <cuda_bf16.h>
#include <cstdint>
#include <math.h>
#define HD 1024
#define NBS 64
#define F_XB 0UL
#define F_T  (F_XB+33554432UL)
#define F_U  (F_T+6291456UL)
#define F_TOT (F_U+6291456UL)
__device__ float g_f[F_TOT];
__device__ __nv_bfloat16 g_b[213909504UL];
__device__ float sp_part3[3*NBS*HD];
__device__ float sp_u3[3*HD], sp_v3[3*HD], sp_w3[3*HD];
__device__ float sp_scale[6];
__device__ float d_rsigma[3];
__device__ unsigned bar_c3[3] = {0,0,0}, bar_g3[3] = {0,0,0};

__device__ __forceinline__ void gbar3(int g) {
    __syncthreads(); __threadfence();
    if (threadIdx.x == 0) {
        unsigned gen = atomicAdd(&bar_g3[g], 0u);
        if (atomicAdd(&bar_c3[g], 1u) == NBS - 1u) {
            bar_c3[g] = 0u; __threadfence(); atomicExch(&bar_g3[g], gen + 1u);
        } else while (atomicAdd(&bar_g3[g], 0u) == gen) __nanosleep(64);
    }
    __syncthreads();
}

__global__ void __launch_bounds__(256) spectral3(const float* __restrict__ WA,
    const float* __restrict__ WB, const float* __restrict__ WC) {
    __shared__ float red[256];
    const int tid = threadIdx.x, g = blockIdx.x >> 6, lb = blockIdx.x & 63;
    const int gtid = lb*256 + tid;
    const float* W = (g==0) ? WA : ((g==1) ? WB : WC);
    float* up = sp_u3 + g*HD;
    float* vp = sp_v3 + g*HD;
    float* wp = sp_w3 + g*HD;
    float* part = sp_part3 + (size_t)g*NBS*HD;
    if (gtid < HD) up[gtid] = 0.03125f;
    if (gtid == 0) sp_scale[g] = 1.f;
    gbar3(g);
    for (int it = 0; it <= 10; it++) {
        {
            const int i0 = lb*16;
            float a0=0,a1=0,a2=0,a3=0;
            for (int i = i0; i < i0+16; i++) {
                float ui = __ldcg(&up[i]);
                const float* Wr = W + (size_t)i*HD;
                a0 += Wr[tid]*ui; a1 += Wr[tid+256]*ui;
                a2 += Wr[tid+512]*ui; a3 += Wr[tid+768]*ui;
            }
            part[lb*HD+tid]=a0; part[lb*HD+tid+256]=a1;
            part[lb*HD+tid+512]=a2; part[lb*HD+tid+768]=a3;
        }
        gbar3(g);
        if (gtid < HD) {
            float s=0;
            for (int b=0;b<NBS;b++) s += __ldcg(&part[b*HD+gtid]);
            vp[gtid] = s * __ldcg(&sp_scale[g]);
        }
        gbar3(g);
        if (lb == 0) {
            float s=0;
            #pragma unroll
            for (int q=0;q<4;q++){ float x=__ldcg(&vp[tid*4+q]); s+=x*x; }
            red[tid]=s; __syncthreads();
            for (int st=128;st>0;st>>=1){ if(tid<st) red[tid]+=red[tid+st]; __syncthreads(); }
            if (tid==0) sp_scale[3+g] = 1.f/(sqrtf(red[0]) + 1e-12f);
        }
        gbar3(g);
        if (it == 10) break;
        {
            float sv = __ldcg(&sp_scale[3+g]);
            const int warp = gtid>>5, lane = gtid&31;
            for (int i = warp; i < HD; i += (NBS*256)/32) {
                const float* Wr = W + (size_t)i*HD;
                float s=0;
                for (int j=lane;j<HD;j+=32) s += Wr[j]*__ldcg(&vp[j]);
                #pragma unroll
                for (int o=16;o;o>>=1) s += __shfl_xor_sync(0xffffffffu,s,o);
                if (lane==0) up[i] = s*sv;
            }
        }
        gbar3(g);
        if (lb == 0) {
            float s=0;
            #pragma unroll
            for (int q=0;q<4;q++){ float x=__ldcg(&up[tid*4+q]); s+=x*x; }
            red[tid]=s; __syncthreads();
            for (int st=128;st>0;st>>=1){ if(tid<st) red[tid]+=red[tid+st]; __syncthreads(); }
            if (tid==0) sp_scale[g] = 1.f/(sqrtf(red[0]) + 1e-12f);
        }
        gbar3(g);
    }
    {
        float sv = __ldcg(&sp_scale[3+g]);
        const int warp = gtid>>5, lane = gtid&31;
        for (int i = warp; i < HD; i += (NBS*256)/32) {
            const float* Wr = W + (size_t)i*HD;
            float s=0;
            for (int j=lane;j<HD;j+=32) s += Wr[j]*__ldcg(&vp[j]);
            #pragma unroll
            for (int o=16;o;o>>=1) s += __shfl_xor_sync(0xffffffffu,s,o);
            if (lane==0) wp[i] = s*sv;
        }
    }
    gbar3(g);
    if (lb == 0) {
        float su = __ldcg(&sp_scale[g]);
        float s=0;
        #pragma unroll
        for (int q=0;q<4;q++) s += __ldcg(&up[tid*4+q])*su*__ldcg(&wp[tid*4+q]);
        red[tid]=s; __syncthreads();
        for (int st=128;st>0;st>>=1){ if(tid<st) red[tid]+=red[tid+st]; __syncthreads(); }
        if (tid==0) d_rsigma[g] = 1.f/red[0];
    }
}

__device__ __forceinline__ void split1(float v, __nv_bfloat16& h, __nv_bfloat16& l) {
    h = __float2bfloat16_rn(v);
    l = __float2bfloat16_rn(v - __bfloat162float(h));
}
__device__ __forceinline__ uint32_t s2u(const void* p) {
    uint32_t a;
    asm("{.reg .u64 t; cvta.to.shared.u64 t, %1; cvt.u32.u64 %0, t;}" : "=r"(a) : "l"(p));
    return a;
}
#define CP16(d,s) asm volatile("cp.async.cg.shared.global [%0], [%1], 16;" :: "r"(d), "l"(s))
#define CPC() asm volatile("cp.async.commit_group;")
#define CPW1() asm volatile("cp.async.wait_group 1;")
#define CPW0() asm volatile("cp.async.wait_group 0;")
#define LDSM4(r0,r1,r2,r3,a) asm volatile("ldmatrix.sync.aligned.m8n8.x4.shared.b16 {%0,%1,%2,%3}, [%4];" \
    : "=r"(r0),"=r"(r1),"=r"(r2),"=r"(r3) : "r"(a))
#define MMA(d,a,b0,b1) asm volatile( \
    "mma.sync.aligned.m16n8k16.row.col.f32.bf16.bf16.f32 {%0,%1,%2,%3},{%4,%5,%6,%7},{%8,%9},{%0,%1,%2,%3};" \
    : "+f"(d[0]),"+f"(d[1]),"+f"(d[2]),"+f"(d[3]) \
    : "r"(a[0]),"r"(a[1]),"r"(a[2]),"r"(a[3]),"r"(b0),"r"(b1))

__global__ void splitk(const float* __restrict__ src, __nv_bfloat16* __restrict__ oh,
                       __nv_bfloat16* __restrict__ ol, int sidx) {
    float f = sidx >= 0 ? d_rsigma[sidx] : 1.f;
    size_t i = ((size_t)blockIdx.x*256 + threadIdx.x)*4;
    float4 v = *(const float4*)(src + i);
    __nv_bfloat16 h0,l0,h1,l1,h2,l2,h3,l3;
    split1(v.x*f,h0,l0); split1(v.y*f,h1,l1); split1(v.z*f,h2,l2); split1(v.w*f,h3,l3);
    __nv_bfloat162 a,b;
    a.x=h0;a.y=h1;b.x=h2;b.y=h3;
    *(__nv_bfloat162*)(oh+i)=a; *(__nv_bfloat162*)(oh+i+2)=b;
    a.x=l0;a.y=l1;b.x=l2;b.y=l3;
    *(__nv_bfloat162*)(ol+i)=a; *(__nv_bfloat162*)(ol+i+2)=b;
}

__global__ void tsplit(const float* __restrict__ W, __nv_bfloat16* __restrict__ oh,
                       __nv_bfloat16* __restrict__ ol, int sidx) {
    __shared__ float t[32][33];
    float s = sidx >= 0 ? d_rsigma[sidx] : 1.f;
    int x = blockIdx.x*32 + threadIdx.x, y0 = blockIdx.y*32;
    #pragma unroll
    for (int i = threadIdx.y; i < 32; i += 8)
        t[i][threadIdx.x] = W[(size_t)(y0+i)*HD + x];
    __syncthreads();
    int ox = y0 + threadIdx.x, oy0 = blockIdx.x*32;
    #pragma unroll
    for (int i = threadIdx.y; i < 32; i += 8) {
        __nv_bfloat16 h,l; split1(t[threadIdx.x][i]*s,h,l);
        oh[(size_t)(oy0+i)*HD + ox] = h;
        ol[(size_t)(oy0+i)*HD + ox] = l;
    }
}

#define STR 40
// mode 0: Cf?/Oh? at r. mode 1: xb scatter (CHUNK=8; bf16 if scan row<4096).
// mode 2: pass3 hs. mode 3: Oh/Ol at r AND O2h/O2l transposed (ladder fused transpose).
__global__ void __launch_bounds__(256,2) mmagemm(
    const __nv_bfloat16* __restrict__ Ahh, const __nv_bfloat16* __restrict__ All,
    const __nv_bfloat16* __restrict__ Bhh, const __nv_bfloat16* __restrict__ Bll,
    const float* __restrict__ Add, float* __restrict__ Cf,
    __nv_bfloat16* __restrict__ Oh, __nv_bfloat16* __restrict__ Ol,
    __nv_bfloat16* __restrict__ O2h, __nv_bfloat16* __restrict__ O2l,
    int mode, int jp)
{
    extern __shared__ __nv_bfloat16 smx[];
    const int tid=threadIdx.x, lane=tid&31, wid=tid>>5, wm=wid&3, wn=wid>>2;
    const int m0=blockIdx.y*128, n0=blockIdx.x*128;
    const uint32_t sb=s2u(smx);
    const __nv_bfloat16* srcs[4]={Ahh,All,Bhh,Bll};
    float acc[2][8][4];
    #pragma unroll
    for (int i=0;i<2;i++)
        #pragma unroll
        for (int j=0;j<8;j++)
            #pragma unroll
            for (int q=0;q<4;q++) acc[i][j][q]=0.f;
    const int lr=tid>>1, lc=(tid&1)*16;
    auto ldst = [&](int kt, int st){
        const int k0 = kt*32;
        #pragma unroll
        for (int a=0;a<4;a++) {
            int row = (a<2 ? m0 : n0) + lr;
            const char* s = (const char*)(srcs[a] + (size_t)row*1024 + k0 + lc);
            uint32_t d = sb + (uint32_t)(st*40960 + a*10240 + (lr*STR+lc)*2);
            CP16(d, s); CP16(d+16, s+16);
        }
    };
    ldst(0,0); CPC();
    for (int kt=0; kt<32; kt++) {
        if (kt<31) { ldst(kt+1,(kt+1)&1); CPC(); CPW1(); } else CPW0();
        __syncthreads();
        const uint32_t ab = sb + (kt&1)*40960;
        #pragma unroll
        for (int kh=0;kh<2;kh++) {
            uint32_t ah[2][4], al[2][4];
            #pragma unroll
            for (int ti=0;ti<2;ti++) {
                uint32_t ad = ab + (uint32_t)(((wm*32+ti*16+(lane&15))*STR + kh*16+(lane>>4)*8)*2);
                LDSM4(ah[ti][0],ah[ti][1],ah[ti][2],ah[ti][3], ad);
                LDSM4(al[ti][0],al[ti][1],al[ti][2],al[ti][3], ad+10240);
            }
            #pragma unroll
            for (int q=0;q<4;q++) {
                uint32_t bd = ab + 20480u + (uint32_t)(((wn*64+q*16+(lane&7)+((lane>>4)&1)*8)*STR + kh*16+((lane>>3)&1)*8)*2);
                uint32_t h0,h1,h2,h3,l0,l1,l2,l3;
                LDSM4(h0,h1,h2,h3, bd);
                LDSM4(l0,l1,l2,l3, bd+10240);
                #pragma unroll
                for (int ti=0;ti<2;ti++) {
                    MMA(acc[ti][q*2],   ah[ti], h0,h1);
                    MMA(acc[ti][q*2+1], ah[ti], h2,h3);
                }
                #pragma unroll
                for (int ti=0;ti<2;ti++) {
                    MMA(acc[ti][q*2],   ah[ti], l0,l1);
                    MMA(acc[ti][q*2+1], ah[ti], l2,l3);
                }
                #pragma unroll
                for (int ti=0;ti<2;ti++) {
                    MMA(acc[ti][q*2],   al[ti], h0,h1);
                    MMA(acc[ti][q*2+1], al[ti], h2,h3);
                }
            }
        }
        __syncthreads();
    }
    const int rb0 = m0 + wm*32 + (lane>>2);
    #pragma unroll
    for (int ti=0;ti<2;ti++)
    #pragma unroll
    for (int j=0;j<8;j++)
    #pragma unroll
    for (int hf=0;hf<2;hf++) {
        int r = rb0 + ti*16 + hf*8;
        int c = n0 + wn*64 + j*8 + (lane&3)*2;
        float v0=acc[ti][j][hf*2], v1=acc[ti][j][hf*2+1];
        if (Add) { float2 ad = *(const float2*)(Add+(size_t)r*1024+c); v0+=ad.x; v1+=ad.y; }
        __nv_bfloat16 h0,l0,h1,l1; split1(v0,h0,l0); split1(v1,h1,l1);
        __nv_bfloat162 ph,pl; ph.x=h0;ph.y=h1; pl.x=l0;pl.y=l1;
        if (mode==2) {
            *(__nv_bfloat162*)(Oh+(size_t)r*1024+c)=ph;
            *(__nv_bfloat162*)(Ol+(size_t)r*1024+c)=pl;
            int k=r>>5, b_=r&31;
            size_t o2=(size_t)b_*1024+(size_t)k*8+jp;
            *(float2*)(Cf+o2*1024+c)=make_float2(v0,v1);
            *(__nv_bfloat162*)(O2h+o2*1024+c)=ph;
            *(__nv_bfloat162*)(O2l+o2*1024+c)=pl;
        } else if (mode==3) {
            *(__nv_bfloat162*)(Oh+(size_t)r*1024+c)=ph;
            *(__nv_bfloat162*)(Ol+(size_t)r*1024+c)=pl;
            O2h[(size_t)c*1024+r]=h0;     O2l[(size_t)c*1024+r]=l0;
            O2h[(size_t)(c+1)*1024+r]=h1; O2l[(size_t)(c+1)*1024+r]=l1;
        } else {
            size_t orow=(size_t)r;
            if (mode==1){ int b_=r>>10,t=r&1023,k=t>>3,jj=t&7; orow=(size_t)((((jj<<7)|k)<<5)|b_); }
            if (Cf) *(float2*)(Cf+orow*1024+c)=make_float2(v0,v1);
            if (Oh && (mode!=1 || orow<4096)) {
                *(__nv_bfloat162*)(Oh+orow*1024+c)=ph;
                *(__nv_bfloat162*)(Ol+orow*1024+c)=pl;
            }
        }
    }
}

__global__ void copy3(float* df, __nv_bfloat16* dh, __nv_bfloat16* dl,
    const float* sf, const __nv_bfloat16* sh, const __nv_bfloat16* sl, int n) {
    int i = blockIdx.x*256 + threadIdx.x;
    if (i < n) { df[i]=sf[i]; dh[i]=sh[i]; dl[i]=sl[i]; }
}
__global__ void zero3(float* f, __nv_bfloat16* h, __nv_bfloat16* l, int n) {
    int i = blockIdx.x*256 + threadIdx.x;
    if (i < n) { f[i]=0.f; h[i]=__float2bfloat16(0.f); l[i]=__float2bfloat16(0.f); }
}

extern "C" void kernel_launch(void* const* d_in, const int* in_sizes, int n_in,
                              void* d_out, int out_size) {
    const float* x  = (const float*)d_in[0];
    const float* WA = (const float*)d_in[1];
    const float* WB = (const float*)d_in[2];
    const float* WC = (const float*)d_in[3];
    float* ys = (float*)d_out;
    float* hs = ys + 33554432UL;
    float* F = nullptr; cudaGetSymbolAddress((void**)&F, g_f);
    __nv_bfloat16* G = nullptr; cudaGetSymbolAddress((void**)&G, g_b);
    float *xb=F+F_XB, *Tf=F+F_T, *Uf=F+F_U;
    __nv_bfloat16* p = G;
    #define NXT(nm,sz) __nv_bfloat16 *nm##h=p, *nm##l=p+(sz); p += 2UL*(sz);
    NXT(X,33554432UL) NXT(WA_,1048576UL) NXT(WB_,1048576UL) NXT(WC_,1048576UL)
    __nv_bfloat16 *Ph[10], *Pl[10];
    Ph[0]=WA_h; Pl[0]=WA_l;
    for (int r=1;r<=9;r++){ Ph[r]=p; Pl[r]=p+1048576UL; p+=2097152UL; }
    NXT(PT0,1048576UL) NXT(PT1,1048576UL)
    NXT(XB0,4194304UL) NXT(S0,4194304UL) NXT(S1,4194304UL)
    __nv_bfloat16 *Th=p, *Tl=p+6291456UL; p+=12582912UL;
    __nv_bfloat16 *Uh=p, *Ul=p+6291456UL; p+=12582912UL;
    NXT(HS,33554432UL)
    #undef NXT

    cudaFuncSetAttribute(mmagemm, cudaFuncAttributeMaxDynamicSharedMemorySize, 81920);

    // launch order puts the big xb mmagemm at OUR launch #5 (ncu capture slot)
    spectral3<<<192, 256>>>(WA, WB, WC);
    splitk<<<32768,256>>>(x, Xh, Xl, -1);
    splitk<<<1024,256>>>(WB, WB_h, WB_l, 1);
    splitk<<<1024,256>>>(WA, WA_h, WA_l, 0);
    mmagemm<<<dim3(8,256),256,81920>>>(Xh,Xl, WB_h,WB_l, nullptr, xb, XB0h,XB0l, nullptr,nullptr, 1,0);
    splitk<<<1024,256>>>(WC, WC_h, WC_l, 2);
    tsplit<<<dim3(32,32), dim3(32,8)>>>(WA, PT0h, PT0l, 0);
    // ladder with fused transpose epilogue (mode 3), PT ping-pong
    __nv_bfloat16 *pth[2]={PT0h,PT1h}, *ptl[2]={PT0l,PT1l};
    for (int r=1;r<=9;r++) {
        mmagemm<<<dim3(8,8),256,81920>>>(Ph[r-1],Pl[r-1], pth[(r-1)&1],ptl[(r-1)&1],
            nullptr, nullptr, Ph[r],Pl[r], pth[r&1],ptl[r&1], 3,0);
    }
    zero3<<<128,256>>>(Tf, Th, Tl, 32768);
    // pass 1: 7 local-scan steps (M=4096); last -> T chunks 1..128
    __nv_bfloat16 *ph_=XB0h, *pl_=XB0l;
    for (int j = 1; j < 8; j++) {
        __nv_bfloat16 *dh = (j==7)?(Th+32768):((j&1)?S1h:S0h);
        __nv_bfloat16 *dl = (j==7)?(Tl+32768):((j&1)?S1l:S0l);
        mmagemm<<<dim3(8,32),256,81920>>>(ph_,pl_, WA_h,WA_l, xb+(size_t)j*4194304UL,
            (j==7)?(Tf+32768):nullptr, dh,dl, nullptr,nullptr, 0,0);
        ph_=dh; pl_=dl;
    }
    // Kogge-Stone over 128 chunks, trimmed grids
    float *cf=Tf, *of=Uf; __nv_bfloat16 *chh=Th,*cll=Tl,*ohh=Uh,*oll=Ul;
    for (int r=0;r<7;r++) {
        int d = 1<<r, n = d*32768;
        int gy = (128 - d + 3) / 4;
        copy3<<<(n+255)/256,256>>>(of, ohh, oll, cf, chh, cll, n);
        mmagemm<<<dim3(8,gy),256,81920>>>(chh,cll, Ph[3+r],Pl[3+r],
            cf+(size_t)n, of+(size_t)n, ohh+(size_t)n, oll+(size_t)n, nullptr,nullptr, 0,0);
        float* tf=cf; cf=of; of=tf;
        __nv_bfloat16 *t1=chh; chh=ohh; ohh=t1;
        __nv_bfloat16 *t2=cll; cll=oll; oll=t2;
    }
    // pass 3: 8 rescan steps with true inits, scatter hs
    ph_=chh; pl_=cll;
    for (int j = 0; j < 8; j++) {
        __nv_bfloat16 *dh = (j&1)?S1h:S0h, *dl = (j&1)?S1l:S0l;
        mmagemm<<<dim3(8,32),256,81920>>>(ph_,pl_, WA_h,WA_l, xb+(size_t)j*4194304UL,
            hs, dh,dl, HSh,HSl, 2,j);
        ph_=dh; pl_=dl;
    }
    mmagemm<<<dim3(8,256),256,81920>>>(HSh,HSl, WC_h,WC_l, nullptr, ys, nullptr,nullptr, nullptr,nullptr, 0,0);
    (void)in_sizes; (void)n_in; (void)out_size;
}